// round 1
// baseline (speedup 1.0000x reference)
#include <cuda_runtime.h>

// Problem constants (fixed shapes from reference setup_inputs)
#define BB  8
#define NN  8192
#define EE  65536
#define DN  64
#define DE  64
#define IUU 128
#define DC  192            // 2*DN + DE
#define BE  (BB*EE)        // 524288
#define BN  (BB*NN)        // 65536

#define TILE_E  32
#define THREADS 256

// Scratch for segment sum / counts (device globals: no allocation allowed)
__device__ float g_sums[(size_t)BN * DN];   // 16 MB
__device__ float g_cnts[BN];                // 256 KB

// ---------------------------------------------------------------------------
__global__ void zero_kernel() {
    int stride = gridDim.x * blockDim.x;
    int i = blockIdx.x * blockDim.x + threadIdx.x;
    for (int j = i; j < BN * DN; j += stride) g_sums[j] = 0.f;
    for (int j = i; j < BN; j += stride)      g_cnts[j] = 0.f;
}

// ---------------------------------------------------------------------------
// Persistent edge kernel: per 32-edge tile
//   cat = [nodes[r] || edge || nodes[s]]  (192)
//   h      = relu(cat @ W_in  + b_in)     (128)
//   e_new  = relu(h   @ W_out + b_out)    (64)   -> atomic segment sum + counts
//   e_out  = relu(e_new @ W_edge + b_edge)(64)   -> global edges_out
// All weights resident in smem for the whole block lifetime.
__global__ __launch_bounds__(THREADS, 1)
void edge_kernel(const float* __restrict__ nodes,
                 const float* __restrict__ edges,
                 const int*   __restrict__ senders,
                 const int*   __restrict__ receivers,
                 const float* __restrict__ W_in,  const float* __restrict__ b_in,
                 const float* __restrict__ W_out, const float* __restrict__ b_out,
                 const float* __restrict__ W_edge,const float* __restrict__ b_edge,
                 float* __restrict__ out_edges)
{
    extern __shared__ float sm[];
    float* Wi  = sm;                       // 192*128 = 24576
    float* Wo  = Wi  + DC * IUU;           // 128*64  = 8192
    float* We  = Wo  + IUU * DN;           // 64*64   = 4096
    float* bi  = We  + DN * DE;            // 128
    float* bo  = bi  + IUU;                // 64
    float* be  = bo  + DN;                 // 64
    float* cat = be  + DE;                 // 32*192 = 6144
    float* hs  = cat + TILE_E * DC;        // 32*128 = 4096
    float* es  = hs  + TILE_E * IUU;       // 32*64  = 2048
    int*   rs  = (int*)(es + TILE_E * DN); // 32
    int*   ss  = rs + TILE_E;              // 32

    const int tid = threadIdx.x;
    const int tx  = tid & 31;              // lane
    const int ty  = tid >> 5;              // warp (0..7)
    const int e_base = ty * 4;             // 4 edges per thread-row

    // ---- load weights/biases once per block ----
    for (int i = tid; i < (DC * IUU) / 4; i += THREADS)
        ((float4*)Wi)[i] = ((const float4*)W_in)[i];
    for (int i = tid; i < (IUU * DN) / 4; i += THREADS)
        ((float4*)Wo)[i] = ((const float4*)W_out)[i];
    for (int i = tid; i < (DN * DE) / 4; i += THREADS)
        ((float4*)We)[i] = ((const float4*)W_edge)[i];
    if (tid < IUU) bi[tid] = b_in[tid];
    if (tid < DN)  bo[tid] = b_out[tid];
    if (tid < DE)  be[tid] = b_edge[tid];

    const int ntiles = BE / TILE_E;        // 16384, exact
    for (int tile = blockIdx.x; tile < ntiles; tile += gridDim.x) {
        const int e0 = tile * TILE_E;
        __syncthreads();  // previous iteration fully done reading cat/hs/es/rs

        if (tid < TILE_E) {
            int ge = e0 + tid;
            int b  = ge >> 16;             // /EE (65536)
            rs[tid] = receivers[ge] + b * NN;
            ss[tid] = senders[ge]   + b * NN;
        }
        __syncthreads();

        // ---- gather concat tile: 32 edges x 48 float4 ----
        for (int i = tid; i < TILE_E * 48; i += THREADS) {
            int e = i / 48, q = i - e * 48;
            float4 v;
            if (q < 16)
                v = ((const float4*)nodes)[(size_t)rs[e] * 16 + q];
            else if (q < 32)
                v = ((const float4*)edges)[(size_t)(e0 + e) * 16 + (q - 16)];
            else
                v = ((const float4*)nodes)[(size_t)ss[e] * 16 + (q - 32)];
            ((float4*)cat)[e * 48 + q] = v;
        }
        __syncthreads();

        // ---- GEMM1: [32,192] @ [192,128] -> h, 4x4 micro-tile ----
        {
            float acc[4][4];
            #pragma unroll
            for (int i = 0; i < 4; i++)
                acc[i][0] = acc[i][1] = acc[i][2] = acc[i][3] = 0.f;
            const float4* wp = ((const float4*)Wi) + tx;
            const float* c0 = cat + (e_base + 0) * DC;
            const float* c1 = cat + (e_base + 1) * DC;
            const float* c2 = cat + (e_base + 2) * DC;
            const float* c3 = cat + (e_base + 3) * DC;
            #pragma unroll 4
            for (int k = 0; k < DC; k++) {
                float4 w = wp[k * 32];
                float a0 = c0[k], a1 = c1[k], a2 = c2[k], a3 = c3[k];
                acc[0][0] += a0 * w.x; acc[0][1] += a0 * w.y; acc[0][2] += a0 * w.z; acc[0][3] += a0 * w.w;
                acc[1][0] += a1 * w.x; acc[1][1] += a1 * w.y; acc[1][2] += a1 * w.z; acc[1][3] += a1 * w.w;
                acc[2][0] += a2 * w.x; acc[2][1] += a2 * w.y; acc[2][2] += a2 * w.z; acc[2][3] += a2 * w.w;
                acc[3][0] += a3 * w.x; acc[3][1] += a3 * w.y; acc[3][2] += a3 * w.z; acc[3][3] += a3 * w.w;
            }
            float4 b4 = ((float4*)bi)[tx];
            #pragma unroll
            for (int i = 0; i < 4; i++) {
                float4 h4;
                h4.x = fmaxf(acc[i][0] + b4.x, 0.f);
                h4.y = fmaxf(acc[i][1] + b4.y, 0.f);
                h4.z = fmaxf(acc[i][2] + b4.z, 0.f);
                h4.w = fmaxf(acc[i][3] + b4.w, 0.f);
                ((float4*)hs)[(e_base + i) * 32 + tx] = h4;
            }
        }
        __syncthreads();

        // ---- GEMM2: [32,128] @ [128,64] -> e_new, 4x2 micro-tile ----
        {
            float acc[4][2];
            #pragma unroll
            for (int i = 0; i < 4; i++) acc[i][0] = acc[i][1] = 0.f;
            const float2* wp = ((const float2*)Wo) + tx;
            const float* h0 = hs + (e_base + 0) * IUU;
            const float* h1 = hs + (e_base + 1) * IUU;
            const float* h2 = hs + (e_base + 2) * IUU;
            const float* h3 = hs + (e_base + 3) * IUU;
            #pragma unroll 4
            for (int k = 0; k < IUU; k++) {
                float2 w = wp[k * 32];
                float a0 = h0[k], a1 = h1[k], a2 = h2[k], a3 = h3[k];
                acc[0][0] += a0 * w.x; acc[0][1] += a0 * w.y;
                acc[1][0] += a1 * w.x; acc[1][1] += a1 * w.y;
                acc[2][0] += a2 * w.x; acc[2][1] += a2 * w.y;
                acc[3][0] += a3 * w.x; acc[3][1] += a3 * w.y;
            }
            float2 b2 = ((float2*)bo)[tx];
            #pragma unroll
            for (int i = 0; i < 4; i++) {
                float v0 = fmaxf(acc[i][0] + b2.x, 0.f);
                float v1 = fmaxf(acc[i][1] + b2.y, 0.f);
                float2 v; v.x = v0; v.y = v1;
                ((float2*)es)[(e_base + i) * 32 + tx] = v;
                int r = rs[e_base + i];
                atomicAdd(&g_sums[(size_t)r * DN + tx * 2 + 0], v0);
                atomicAdd(&g_sums[(size_t)r * DN + tx * 2 + 1], v1);
                if (tx == 0) atomicAdd(&g_cnts[r], 1.0f);
            }
        }
        __syncthreads();

        // ---- GEMM3: [32,64] @ [64,64] -> edges_out, 4x2 micro-tile ----
        {
            float acc[4][2];
            #pragma unroll
            for (int i = 0; i < 4; i++) acc[i][0] = acc[i][1] = 0.f;
            const float2* wp = ((const float2*)We) + tx;
            const float* v0p = es + (e_base + 0) * DN;
            const float* v1p = es + (e_base + 1) * DN;
            const float* v2p = es + (e_base + 2) * DN;
            const float* v3p = es + (e_base + 3) * DN;
            #pragma unroll 4
            for (int k = 0; k < DN; k++) {
                float2 w = wp[k * 32];
                float a0 = v0p[k], a1 = v1p[k], a2 = v2p[k], a3 = v3p[k];
                acc[0][0] += a0 * w.x; acc[0][1] += a0 * w.y;
                acc[1][0] += a1 * w.x; acc[1][1] += a1 * w.y;
                acc[2][0] += a2 * w.x; acc[2][1] += a2 * w.y;
                acc[3][0] += a3 * w.x; acc[3][1] += a3 * w.y;
            }
            float2 b2 = ((float2*)be)[tx];
            #pragma unroll
            for (int i = 0; i < 4; i++) {
                float2 v;
                v.x = fmaxf(acc[i][0] + b2.x, 0.f);
                v.y = fmaxf(acc[i][1] + b2.y, 0.f);
                ((float2*)(out_edges + (size_t)(e0 + e_base + i) * DE))[tx] = v;
            }
        }
    }
}

// ---------------------------------------------------------------------------
__global__ void finalize_kernel(float* __restrict__ out_nodes) {
    int i = blockIdx.x * blockDim.x + threadIdx.x;
    if (i < BN * DN) {
        float c = g_cnts[i >> 6];
        out_nodes[i] = (c > 0.f) ? (g_sums[i] / c) : 0.f;
    }
}

__global__ void sr_kernel(const int* __restrict__ s, const int* __restrict__ r,
                          float* __restrict__ os, float* __restrict__ orr) {
    int i = blockIdx.x * blockDim.x + threadIdx.x;
    if (i < BE) {
        os[i]  = (float)s[i];
        orr[i] = (float)r[i];
    }
}

// ---------------------------------------------------------------------------
static const int SMEM_BYTES =
    (DC * IUU + IUU * DN + DN * DE + IUU + DN + DE +
     TILE_E * DC + TILE_E * IUU + TILE_E * DN) * (int)sizeof(float) +
    2 * TILE_E * (int)sizeof(int);   // = 197,888 bytes

extern "C" void kernel_launch(void* const* d_in, const int* in_sizes, int n_in,
                              void* d_out, int out_size) {
    const float* nodes     = (const float*)d_in[0];
    const float* edges     = (const float*)d_in[1];
    const int*   senders   = (const int*)  d_in[2];
    const int*   receivers = (const int*)  d_in[3];
    const float* W_in      = (const float*)d_in[4];
    const float* b_in      = (const float*)d_in[5];
    const float* W_out     = (const float*)d_in[6];
    const float* b_out     = (const float*)d_in[7];
    const float* W_edge    = (const float*)d_in[8];
    const float* b_edge    = (const float*)d_in[9];

    float* out       = (float*)d_out;
    float* out_nodes = out;                                  // BN*DN
    float* out_edges = out_nodes + (size_t)BN * DN;          // BE*DE
    float* out_s     = out_edges + (size_t)BE * DE;          // BE
    float* out_r     = out_s + BE;                           // BE

    cudaFuncSetAttribute(edge_kernel,
                         cudaFuncAttributeMaxDynamicSharedMemorySize, SMEM_BYTES);

    int sm_count = 148;
    cudaDeviceGetAttribute(&sm_count, cudaDevAttrMultiProcessorCount, 0);

    zero_kernel<<<1024, 256>>>();
    edge_kernel<<<sm_count, THREADS, SMEM_BYTES>>>(
        nodes, edges, senders, receivers,
        W_in, b_in, W_out, b_out, W_edge, b_edge, out_edges);
    finalize_kernel<<<(BN * DN + 255) / 256, 256>>>(out_nodes);
    sr_kernel<<<(BE + 255) / 256, 256>>>(senders, receivers, out_s, out_r);
}

// round 3
// speedup vs baseline: 3.1754x; 3.1754x over previous
#include <cuda_runtime.h>
#include <cuda_bf16.h>
#include <cstdint>

// Problem constants
#define NNODES 8192
#define DN  64
#define DE  64
#define IUU 128
#define BE  524288
#define BN  65536
#define TILE 128
#define NTILES (BE / TILE)     // 4096
#define THREADS 256

// Scratch for segment sum / counts (device globals: no allocation allowed)
__device__ float g_sums[(size_t)BN * DN];   // 16 MB
__device__ float g_cnts[BN];

// ---------------- smem layout (bytes) ----------------
#define SM_RS   0                       // 128 ints
#define SM_SS   512
#define SM_BI   1024                    // 128 f
#define SM_BO   1536                    // 64 f
#define SM_BE2  1792                    // 64 f
#define SM_W1   2048                    // GEMM1 B-frags: 12s*16j*2p*256B = 98304
#define SM_W2   (SM_W1 + 98304)         // GEMM2: 8s*8j*2p*256 = 32768
#define SM_W3   (SM_W2 + 32768)         // GEMM3: 4s*8j*2p*256 = 16384
#define SM_AB   (SM_W3 + 16384)         // activation frag buffer, 65536
#define SMEM_TOTAL (SM_AB + 65536)      // 215040

// ---------------------------------------------------------------------------
__device__ __forceinline__ void mma_bf16(float* c, const uint32_t* a,
                                         uint32_t b0, uint32_t b1) {
    asm volatile(
        "mma.sync.aligned.m16n8k16.row.col.f32.bf16.bf16.f32 "
        "{%0,%1,%2,%3},{%4,%5,%6,%7},{%8,%9},{%0,%1,%2,%3};"
        : "+f"(c[0]), "+f"(c[1]), "+f"(c[2]), "+f"(c[3])
        : "r"(a[0]), "r"(a[1]), "r"(a[2]), "r"(a[3]), "r"(b0), "r"(b1));
}

// fp32 pair -> packed bf16 hi pair + packed bf16 residual pair
__device__ __forceinline__ void split2(float x, float y, uint32_t& hi, uint32_t& mid) {
    __nv_bfloat162 h = __floats2bfloat162_rn(x, y);     // .x = x (low 16 bits)
    float rx = x - __bfloat162float(h.x);
    float ry = y - __bfloat162float(h.y);
    __nv_bfloat162 m = __floats2bfloat162_rn(rx, ry);
    hi  = *reinterpret_cast<uint32_t*>(&h);
    mid = *reinterpret_cast<uint32_t*>(&m);
}

// Preload weights into B-fragment layout (split hi/mid). W is [K, NT*8] row-major.
// Frag (s,j): 32 lanes x 2 regs; reg r: k-pair (16s+2t+8r, +1), n = 8j+g.
__device__ __forceinline__ void load_wfrag(const float* __restrict__ W, int K, int NT,
                                           char* dst, int wid, int lane) {
    const int g = lane >> 2, t = lane & 3;
    const int Nw = NT * 8;
    const int SF = K / 16;
    for (int f = wid; f < SF * NT; f += (THREADS / 32)) {
        int s = f / NT, j = f - s * NT;
        int n = j * 8 + g;
        #pragma unroll
        for (int r = 0; r < 2; r++) {
            int k = s * 16 + 2 * t + 8 * r;
            float x = W[(size_t)k * Nw + n];
            float y = W[(size_t)(k + 1) * Nw + n];
            uint32_t hi, mid;
            split2(x, y, hi, mid);
            char* p = dst + (size_t)(f * 2) * 256 + lane * 8 + r * 4;
            *(uint32_t*)p         = hi;
            *(uint32_t*)(p + 256) = mid;
        }
    }
}

// ---------------------------------------------------------------------------
__global__ void zero_kernel() {
    int stride = gridDim.x * blockDim.x;
    int i = blockIdx.x * blockDim.x + threadIdx.x;
    for (int j = i; j < BN * DN; j += stride) g_sums[j] = 0.f;
    for (int j = i; j < BN; j += stride)      g_cnts[j] = 0.f;
}

// ---------------------------------------------------------------------------
__global__ __launch_bounds__(THREADS, 1)
void edge_kernel(const float* __restrict__ nodes,
                 const float* __restrict__ edges,
                 const int*   __restrict__ senders,
                 const int*   __restrict__ receivers,
                 const float* __restrict__ W_in,  const float* __restrict__ b_in,
                 const float* __restrict__ W_out, const float* __restrict__ b_out,
                 const float* __restrict__ W_edge,const float* __restrict__ b_edge,
                 float* __restrict__ out_edges)
{
    extern __shared__ char sm[];
    const int tid  = threadIdx.x;
    const int lane = tid & 31;
    const int wid  = tid >> 5;
    const int g = lane >> 2, t = lane & 3;
    const int wm = wid & 3;                 // M band: rows 32*wm
    const int wn = wid >> 2;                // N half

    // ---- one-time: weights into frag layout, biases ----
    load_wfrag(W_in,   192, 16, sm + SM_W1, wid, lane);
    load_wfrag(W_out,  128,  8, sm + SM_W2, wid, lane);
    load_wfrag(W_edge,  64,  8, sm + SM_W3, wid, lane);
    if (tid < IUU) ((float*)(sm + SM_BI))[tid]  = b_in[tid];
    if (tid < DN)  ((float*)(sm + SM_BO))[tid]  = b_out[tid];
    if (tid < DE)  ((float*)(sm + SM_BE2))[tid] = b_edge[tid];

    int* rs  = (int*)(sm + SM_RS);
    int* ssn = (int*)(sm + SM_SS);
    const float* bi = (const float*)(sm + SM_BI);
    const float* bo = (const float*)(sm + SM_BO);
    const float* be = (const float*)(sm + SM_BE2);

    for (int tile = blockIdx.x; tile < NTILES; tile += gridDim.x) {
        const int e0 = tile * TILE;
        __syncthreads();                       // protect rs/ss + AB reuse
        if (tid < TILE) {
            int ge = e0 + tid, b = ge >> 16;   // / 65536 edges per graph
            int rr = receivers[ge] + b * NNODES;
            rs[tid]  = rr;
            ssn[tid] = senders[ge] + b * NNODES;
            atomicAdd(&g_cnts[rr], 1.0f);
        }
        __syncthreads();

        // =================== GEMM1: cat[128,192] @ W_in -> C1[128,128] =======
        float C1[2][8][4];
        #pragma unroll
        for (int a = 0; a < 2; a++)
            #pragma unroll
            for (int b = 0; b < 8; b++)
                #pragma unroll
                for (int c = 0; c < 4; c++) C1[a][b][c] = 0.f;

        #pragma unroll
        for (int kc = 0; kc < 3; kc++) {
            // ---- gather 64-col chunk, split, store A-frags ----
            #pragma unroll
            for (int ii = 0; ii < 16; ii++) {
                int idx = tid + ii * THREADS;      // 4096 float2 units
                int e = idx >> 5, j = idx & 31;    // j = lane (warp-uniform e)
                const float* base =
                    (kc == 0) ? nodes + (size_t)rs[e]  * DN :
                    (kc == 1) ? edges + (size_t)(e0+e) * DE :
                                nodes + (size_t)ssn[e] * DN;
                float2 v = ((const float2*)base)[j];
                uint32_t hi, mid;
                split2(v.x, v.y, hi, mid);
                int mt = e >> 4, sl = j >> 3;
                int ln = ((e & 7) << 2) | (j & 3);
                int rg = ((e >> 3) & 1) | (((j >> 2) & 1) << 1);
                char* p = sm + SM_AB + (((mt << 2) + sl) << 9) + ln * 16 + rg * 4;
                *(uint32_t*)p            = hi;
                *(uint32_t*)(p + 16384)  = mid;    // mid region
            }
            __syncthreads();
            // ---- mma accumulate ----
            #pragma unroll
            for (int sl = 0; sl < 4; sl++) {
                uint4 Ah[2], Am[2];
                #pragma unroll
                for (int m2 = 0; m2 < 2; m2++) {
                    int mt = (wm << 1) + m2;
                    const char* p = sm + SM_AB + (((mt << 2) + sl) << 9) + lane * 16;
                    Ah[m2] = *(const uint4*)p;
                    Am[m2] = *(const uint4*)(p + 16384);
                }
                int s = (kc << 2) + sl;
                #pragma unroll
                for (int j8 = 0; j8 < 8; j8++) {
                    int jg = (wn << 3) + j8;
                    const char* wb = sm + SM_W1 + (size_t)((s * 16 + jg) * 2) * 256 + lane * 8;
                    uint2 Bh = *(const uint2*)wb;
                    uint2 Bm = *(const uint2*)(wb + 256);
                    #pragma unroll
                    for (int m2 = 0; m2 < 2; m2++) {
                        mma_bf16(C1[m2][j8], (const uint32_t*)&Ah[m2], Bh.x, Bh.y);
                        mma_bf16(C1[m2][j8], (const uint32_t*)&Ah[m2], Bm.x, Bm.y);
                        mma_bf16(C1[m2][j8], (const uint32_t*)&Am[m2], Bh.x, Bh.y);
                    }
                }
            }
            __syncthreads();
        }

        // ---- epilogue1: bias+relu -> h frags (full 64KB: hi @0, mid @32768) ----
        #pragma unroll
        for (int m2 = 0; m2 < 2; m2++) {
            int mt = (wm << 1) + m2;
            #pragma unroll
            for (int j8e = 0; j8e < 8; j8e += 2) {
                uint4 Hh, Hm;
                uint32_t* hh = (uint32_t*)&Hh;
                uint32_t* hm = (uint32_t*)&Hm;
                #pragma unroll
                for (int q = 0; q < 2; q++) {
                    int j8 = j8e + q;
                    int col = (((wn << 3) + j8) << 3) + (t << 1);
                    float v0 = fmaxf(C1[m2][j8][0] + bi[col],     0.f);
                    float v1 = fmaxf(C1[m2][j8][1] + bi[col + 1], 0.f);
                    float v2 = fmaxf(C1[m2][j8][2] + bi[col],     0.f);
                    float v3 = fmaxf(C1[m2][j8][3] + bi[col + 1], 0.f);
                    split2(v0, v1, hh[q * 2],     hm[q * 2]);
                    split2(v2, v3, hh[q * 2 + 1], hm[q * 2 + 1]);
                }
                int s2 = ((wn << 3) + j8e) >> 1;
                char* p = sm + SM_AB + (((mt << 3) + s2) << 9) + lane * 16;
                *(uint4*)p            = Hh;
                *(uint4*)(p + 32768)  = Hm;
            }
        }
        __syncthreads();

        // =================== GEMM2: h[128,128] @ W_out -> C2[128,64] =========
        float C2[2][4][4];
        #pragma unroll
        for (int a = 0; a < 2; a++)
            #pragma unroll
            for (int b = 0; b < 4; b++)
                #pragma unroll
                for (int c = 0; c < 4; c++) C2[a][b][c] = 0.f;
        #pragma unroll
        for (int s2 = 0; s2 < 8; s2++) {
            uint4 Ah[2], Am[2];
            #pragma unroll
            for (int m2 = 0; m2 < 2; m2++) {
                int mt = (wm << 1) + m2;
                const char* p = sm + SM_AB + (((mt << 3) + s2) << 9) + lane * 16;
                Ah[m2] = *(const uint4*)p;
                Am[m2] = *(const uint4*)(p + 32768);
            }
            #pragma unroll
            for (int j4 = 0; j4 < 4; j4++) {
                int jg = (wn << 2) + j4;
                const char* wb = sm + SM_W2 + (size_t)((s2 * 8 + jg) * 2) * 256 + lane * 8;
                uint2 Bh = *(const uint2*)wb;
                uint2 Bm = *(const uint2*)(wb + 256);
                #pragma unroll
                for (int m2 = 0; m2 < 2; m2++) {
                    mma_bf16(C2[m2][j4], (const uint32_t*)&Ah[m2], Bh.x, Bh.y);
                    mma_bf16(C2[m2][j4], (const uint32_t*)&Ah[m2], Bm.x, Bm.y);
                    mma_bf16(C2[m2][j4], (const uint32_t*)&Am[m2], Bh.x, Bh.y);
                }
            }
        }
        __syncthreads();

        // ---- epilogue2: bias+relu -> atomics + e_new frags (first 32KB) ----
        #pragma unroll
        for (int m2 = 0; m2 < 2; m2++) {
            int r0 = (wm << 5) + (m2 << 4) + g;
            int n0 = rs[r0], n1 = rs[r0 + 8];
            int mt = (wm << 1) + m2;
            #pragma unroll
            for (int j4e = 0; j4e < 4; j4e += 2) {
                uint4 Eh, Em;
                uint32_t* eh = (uint32_t*)&Eh;
                uint32_t* em = (uint32_t*)&Em;
                #pragma unroll
                for (int q = 0; q < 2; q++) {
                    int j4 = j4e + q;
                    int col = (((wn << 2) + j4) << 3) + (t << 1);
                    float v0 = fmaxf(C2[m2][j4][0] + bo[col],     0.f);
                    float v1 = fmaxf(C2[m2][j4][1] + bo[col + 1], 0.f);
                    float v2 = fmaxf(C2[m2][j4][2] + bo[col],     0.f);
                    float v3 = fmaxf(C2[m2][j4][3] + bo[col + 1], 0.f);
                    atomicAdd(&g_sums[(size_t)n0 * DN + col],     v0);
                    atomicAdd(&g_sums[(size_t)n0 * DN + col + 1], v1);
                    atomicAdd(&g_sums[(size_t)n1 * DN + col],     v2);
                    atomicAdd(&g_sums[(size_t)n1 * DN + col + 1], v3);
                    split2(v0, v1, eh[q * 2],     em[q * 2]);
                    split2(v2, v3, eh[q * 2 + 1], em[q * 2 + 1]);
                }
                int s3 = ((wn << 2) + j4e) >> 1;
                char* p = sm + SM_AB + (((mt << 2) + s3) << 9) + lane * 16;
                *(uint4*)p           = Eh;
                *(uint4*)(p + 16384) = Em;
            }
        }
        __syncthreads();

        // =================== GEMM3: e[128,64] @ W_edge -> C3[128,64] =========
        float C3[2][4][4];
        #pragma unroll
        for (int a = 0; a < 2; a++)
            #pragma unroll
            for (int b = 0; b < 4; b++)
                #pragma unroll
                for (int c = 0; c < 4; c++) C3[a][b][c] = 0.f;
        #pragma unroll
        for (int s3 = 0; s3 < 4; s3++) {
            uint4 Ah[2], Am[2];
            #pragma unroll
            for (int m2 = 0; m2 < 2; m2++) {
                int mt = (wm << 1) + m2;
                const char* p = sm + SM_AB + (((mt << 2) + s3) << 9) + lane * 16;
                Ah[m2] = *(const uint4*)p;
                Am[m2] = *(const uint4*)(p + 16384);
            }
            #pragma unroll
            for (int j4 = 0; j4 < 4; j4++) {
                int jg = (wn << 2) + j4;
                const char* wb = sm + SM_W3 + (size_t)((s3 * 8 + jg) * 2) * 256 + lane * 8;
                uint2 Bh = *(const uint2*)wb;
                uint2 Bm = *(const uint2*)(wb + 256);
                #pragma unroll
                for (int m2 = 0; m2 < 2; m2++) {
                    mma_bf16(C3[m2][j4], (const uint32_t*)&Ah[m2], Bh.x, Bh.y);
                    mma_bf16(C3[m2][j4], (const uint32_t*)&Ah[m2], Bm.x, Bm.y);
                    mma_bf16(C3[m2][j4], (const uint32_t*)&Am[m2], Bh.x, Bh.y);
                }
            }
        }

        // ---- epilogue3: bias+relu -> gmem ----
        #pragma unroll
        for (int m2 = 0; m2 < 2; m2++) {
            int row = e0 + (wm << 5) + (m2 << 4) + g;
            #pragma unroll
            for (int j4 = 0; j4 < 4; j4++) {
                int col = (((wn << 2) + j4) << 3) + (t << 1);
                float2 va, vb;
                va.x = fmaxf(C3[m2][j4][0] + be[col],     0.f);
                va.y = fmaxf(C3[m2][j4][1] + be[col + 1], 0.f);
                vb.x = fmaxf(C3[m2][j4][2] + be[col],     0.f);
                vb.y = fmaxf(C3[m2][j4][3] + be[col + 1], 0.f);
                *(float2*)(out_edges + (size_t)row       * DE + col) = va;
                *(float2*)(out_edges + (size_t)(row + 8) * DE + col) = vb;
            }
        }
    }
}

// ---------------------------------------------------------------------------
__global__ void finalize_kernel(float* __restrict__ out_nodes) {
    int i = blockIdx.x * blockDim.x + threadIdx.x;
    if (i < BN * DN) {
        float c = g_cnts[i >> 6];
        out_nodes[i] = (c > 0.f) ? (g_sums[i] / c) : 0.f;
    }
}

__global__ void sr_kernel(const int* __restrict__ s, const int* __restrict__ r,
                          float* __restrict__ os, float* __restrict__ orr) {
    int i = blockIdx.x * blockDim.x + threadIdx.x;
    if (i < BE) {
        os[i]  = (float)s[i];
        orr[i] = (float)r[i];
    }
}

// ---------------------------------------------------------------------------
extern "C" void kernel_launch(void* const* d_in, const int* in_sizes, int n_in,
                              void* d_out, int out_size) {
    const float* nodes     = (const float*)d_in[0];
    const float* edges     = (const float*)d_in[1];
    const int*   senders   = (const int*)  d_in[2];
    const int*   receivers = (const int*)  d_in[3];
    const float* W_in      = (const float*)d_in[4];
    const float* b_in      = (const float*)d_in[5];
    const float* W_out     = (const float*)d_in[6];
    const float* b_out     = (const float*)d_in[7];
    const float* W_edge    = (const float*)d_in[8];
    const float* b_edge    = (const float*)d_in[9];

    float* out       = (float*)d_out;
    float* out_nodes = out;
    float* out_edges = out_nodes + (size_t)BN * DN;
    float* out_s     = out_edges + (size_t)BE * DE;
    float* out_r     = out_s + BE;

    cudaFuncSetAttribute(edge_kernel,
                         cudaFuncAttributeMaxDynamicSharedMemorySize, SMEM_TOTAL);

    int sm_count = 148;
    cudaDeviceGetAttribute(&sm_count, cudaDevAttrMultiProcessorCount, 0);

    zero_kernel<<<1024, 256>>>();
    edge_kernel<<<sm_count, THREADS, SMEM_TOTAL>>>(
        nodes, edges, senders, receivers,
        W_in, b_in, W_out, b_out, W_edge, b_edge, out_edges);
    finalize_kernel<<<(BN * DN + 255) / 256, 256>>>(out_nodes);
    sr_kernel<<<(BE + 255) / 256, 256>>>(senders, receivers, out_s, out_r);
}

// round 4
// speedup vs baseline: 3.7958x; 1.1954x over previous
#include <cuda_runtime.h>
#include <cuda_bf16.h>
#include <cstdint>

// Problem constants
#define NNODES 8192
#define DN  64
#define DE  64
#define IUU 128
#define BE  524288
#define BN  65536
#define TILE 128
#define NTILES (BE / TILE)     // 4096
#define THREADS 256

// Device-global scratch (no allocation allowed)
__device__ float g_sums[(size_t)BN * DN];    // 16 MB
__device__ float g_cnts[BN];
__device__ float g_P[(size_t)BN * 256];      // 64 MB: [P_r(128) || P_s(128)] per node

// ---------------- edge-kernel smem layout (bytes) ----------------
#define SM_RS   0                        // 2 x 128 ints (double buffered)
#define SM_SS   1024                     // 2 x 128 ints
#define SM_BO   2048                     // 64 f
#define SM_BE2  2304                     // 64 f
#define SM_W1   4096                     // edge part of W_in: 4s*16j*512 = 32768
#define SM_W2   36864                    // 8s*8j*512 = 32768
#define SM_W3   69632                    // 4s*8j*512 = 16384
#define SM_AB   86016                    // h frags 64K (hi + mid@+32768); e frags overlay 32K (mid@+16384)
#define SM_PING 151552                   // 2 x 32768 edge-chunk frag buffers (hi + mid@+16384)
#define SMEM_TOTAL 217088

// ---------------- pnode-kernel smem layout ----------------
#define PSM_W   0                        // 4s*32j*512 = 65536
#define PSM_A   65536                    // 32768 (hi + mid@+16384)
#define PSM_B   98304                    // 128 f bias
#define PSM_TOTAL 98816

// ---------------------------------------------------------------------------
__device__ __forceinline__ void mma_bf16(float* c, const uint32_t* a,
                                         uint32_t b0, uint32_t b1) {
    asm volatile(
        "mma.sync.aligned.m16n8k16.row.col.f32.bf16.bf16.f32 "
        "{%0,%1,%2,%3},{%4,%5,%6,%7},{%8,%9},{%0,%1,%2,%3};"
        : "+f"(c[0]), "+f"(c[1]), "+f"(c[2]), "+f"(c[3])
        : "r"(a[0]), "r"(a[1]), "r"(a[2]), "r"(a[3]), "r"(b0), "r"(b1));
}

__device__ __forceinline__ void split2(float x, float y, uint32_t& hi, uint32_t& mid) {
    __nv_bfloat162 h = __floats2bfloat162_rn(x, y);
    float rx = x - __bfloat162float(h.x);
    float ry = y - __bfloat162float(h.y);
    __nv_bfloat162 m = __floats2bfloat162_rn(rx, ry);
    hi  = *reinterpret_cast<uint32_t*>(&h);
    mid = *reinterpret_cast<uint32_t*>(&m);
}

// Weights -> B-frag layout, hi/mid interleaved per 16B: {hi0,hi1,mid0,mid1}.
// W is [K, Nw] row-major; frag (s,j): n = 8j+g, reg r: k = 16s+2t+8r.
__device__ __forceinline__ void load_wfrag(const float* __restrict__ W, int K, int NT,
                                           char* dst, int wid, int lane) {
    const int g = lane >> 2, t = lane & 3;
    const int Nw = NT * 8;
    const int SF = K / 16;
    for (int f = wid; f < SF * NT; f += (THREADS / 32)) {
        int s = f / NT, j = f - s * NT;
        int n = j * 8 + g;
        uint4 v;
        uint32_t* vp = (uint32_t*)&v;
        #pragma unroll
        for (int r = 0; r < 2; r++) {
            int k = s * 16 + 2 * t + 8 * r;
            split2(W[(size_t)k * Nw + n], W[(size_t)(k + 1) * Nw + n], vp[r], vp[2 + r]);
        }
        *(uint4*)(dst + (size_t)f * 512 + lane * 16) = v;
    }
}

// ---------------------------------------------------------------------------
__global__ void zero_kernel() {
    int stride = gridDim.x * blockDim.x;
    int i = blockIdx.x * blockDim.x + threadIdx.x;
    for (int j = i; j < BN * DN; j += stride) g_sums[j] = 0.f;
    for (int j = i; j < BN; j += stride)      g_cnts[j] = 0.f;
}

// ---------------------------------------------------------------------------
// P[n][0:128)   = nodes[n] @ W_in[0:64]   + b_in   (receiver part)
// P[n][128:256) = nodes[n] @ W_in[128:192]         (sender part)
__global__ __launch_bounds__(THREADS, 1)
void pnode_kernel(const float* __restrict__ nodes,
                  const float* __restrict__ W_in,
                  const float* __restrict__ b_in)
{
    extern __shared__ char sm[];
    const int tid  = threadIdx.x;
    const int lane = tid & 31;
    const int wid  = tid >> 5;
    const int g = lane >> 2, t = lane & 3;
    const int wm = wid & 3;
    const int wn = wid >> 2;

    // weights: Wbig[k][n], k<64; n<128 -> W_in[k][n]; else W_in[128+k][n-128]
    for (int f = wid; f < 4 * 32; f += (THREADS / 32)) {
        int s = f >> 5, j = f & 31;
        int n = j * 8 + g;
        uint4 v;
        uint32_t* vp = (uint32_t*)&v;
        #pragma unroll
        for (int r = 0; r < 2; r++) {
            int k = s * 16 + 2 * t + 8 * r;
            float x, y;
            if (n < 128) { x = W_in[(size_t)k * IUU + n];         y = W_in[(size_t)(k + 1) * IUU + n]; }
            else         { x = W_in[(size_t)(128 + k) * IUU + n - 128];
                           y = W_in[(size_t)(129 + k) * IUU + n - 128]; }
            split2(x, y, vp[r], vp[2 + r]);
        }
        *(uint4*)(sm + PSM_W + (size_t)f * 512 + lane * 16) = v;
    }
    if (tid < IUU) ((float*)(sm + PSM_B))[tid] = b_in[tid];

    // gather A: 128 node rows x 64 cols
    const int m0 = blockIdx.x * 128;
    #pragma unroll
    for (int ii = 0; ii < 16; ii++) {
        int idx = tid + ii * THREADS;
        int e = idx >> 5, j = idx & 31;
        float2 v = ((const float2*)(nodes + (size_t)(m0 + e) * DN))[j];
        uint32_t hi, mid;
        split2(v.x, v.y, hi, mid);
        int mt = e >> 4, sl = j >> 3;
        int ln = ((e & 7) << 2) | (j & 3);
        int rg = ((e >> 3) & 1) | (((j >> 2) & 1) << 1);
        char* p = sm + PSM_A + (((mt << 2) + sl) << 9) + ln * 16 + rg * 4;
        *(uint32_t*)p           = hi;
        *(uint32_t*)(p + 16384) = mid;
    }
    __syncthreads();

    const float* bi = (const float*)(sm + PSM_B);
    #pragma unroll
    for (int np = 0; np < 2; np++) {           // two N passes of 64 cols each
        float C[2][8][4];
        #pragma unroll
        for (int a = 0; a < 2; a++)
            #pragma unroll
            for (int b = 0; b < 8; b++)
                #pragma unroll
                for (int c = 0; c < 4; c++) C[a][b][c] = 0.f;
        #pragma unroll
        for (int sl = 0; sl < 4; sl++) {
            uint4 Ah[2], Am[2];
            #pragma unroll
            for (int m2 = 0; m2 < 2; m2++) {
                int mt = (wm << 1) + m2;
                const char* p = sm + PSM_A + (((mt << 2) + sl) << 9) + lane * 16;
                Ah[m2] = *(const uint4*)p;
                Am[m2] = *(const uint4*)(p + 16384);
            }
            #pragma unroll
            for (int j8 = 0; j8 < 8; j8++) {
                int jg = wn * 16 + np * 8 + j8;
                uint4 B = *(const uint4*)(sm + PSM_W + (size_t)(sl * 32 + jg) * 512 + lane * 16);
                #pragma unroll
                for (int m2 = 0; m2 < 2; m2++) {
                    mma_bf16(C[m2][j8], (const uint32_t*)&Ah[m2], B.x, B.y);
                    mma_bf16(C[m2][j8], (const uint32_t*)&Ah[m2], B.z, B.w);
                    mma_bf16(C[m2][j8], (const uint32_t*)&Am[m2], B.x, B.y);
                }
            }
        }
        #pragma unroll
        for (int m2 = 0; m2 < 2; m2++) {
            int row = m0 + wm * 32 + m2 * 16 + g;
            #pragma unroll
            for (int j8 = 0; j8 < 8; j8++) {
                int col = (wn * 16 + np * 8 + j8) * 8 + t * 2;
                float bx = (col < 128) ? bi[col]     : 0.f;
                float by = (col < 128) ? bi[col + 1] : 0.f;
                float2 va, vb;
                va.x = C[m2][j8][0] + bx; va.y = C[m2][j8][1] + by;
                vb.x = C[m2][j8][2] + bx; vb.y = C[m2][j8][3] + by;
                *(float2*)(g_P + (size_t)row * 256 + col)       = va;
                *(float2*)(g_P + (size_t)(row + 8) * 256 + col) = vb;
            }
        }
    }
}

// ---------------------------------------------------------------------------
__global__ __launch_bounds__(THREADS, 1)
void edge_kernel(const float* __restrict__ edges,
                 const int*   __restrict__ senders,
                 const int*   __restrict__ receivers,
                 const float* __restrict__ W_in,
                 const float* __restrict__ W_out, const float* __restrict__ b_out,
                 const float* __restrict__ W_edge,const float* __restrict__ b_edge,
                 float* __restrict__ out_edges)
{
    extern __shared__ char sm[];
    const int tid  = threadIdx.x;
    const int lane = tid & 31;
    const int wid  = tid >> 5;
    const int g = lane >> 2, t = lane & 3;
    const int wm = wid & 3;
    const int wn = wid >> 2;

    // one-time: weights (W_in edge part = rows 64..127), biases
    load_wfrag(W_in + 64 * IUU, 64, 16, sm + SM_W1, wid, lane);
    load_wfrag(W_out, 128, 8, sm + SM_W2, wid, lane);
    load_wfrag(W_edge, 64, 8, sm + SM_W3, wid, lane);
    if (tid < DN) ((float*)(sm + SM_BO))[tid]  = b_out[tid];
    if (tid < DE) ((float*)(sm + SM_BE2))[tid] = b_edge[tid];

    const float* bo = (const float*)(sm + SM_BO);
    const float* be = (const float*)(sm + SM_BE2);

    // prologue: tile0 indices + edge chunk into buffer 0
    {
        int tile0 = blockIdx.x;
        if (tid < TILE) {
            int ge = tile0 * TILE + tid, b = ge >> 16;
            int nr = receivers[ge] + (b << 13);
            ((int*)(sm + SM_RS))[tid] = nr;
            ((int*)(sm + SM_SS))[tid] = senders[ge] + (b << 13);
            atomicAdd(&g_cnts[nr], 1.0f);
        }
        const float2* ebase = (const float2*)(edges + (size_t)tile0 * TILE * DE);
        #pragma unroll
        for (int ii = 0; ii < 16; ii++) {
            int idx = tid + ii * THREADS;
            float2 v = ebase[idx];
            uint32_t hi, mid;
            split2(v.x, v.y, hi, mid);
            int e = idx >> 5, j = idx & 31;
            int mt = e >> 4, sl = j >> 3;
            int ln = ((e & 7) << 2) | (j & 3);
            int rg = ((e >> 3) & 1) | (((j >> 2) & 1) << 1);
            char* p = sm + SM_PING + (((mt << 2) + sl) << 9) + ln * 16 + rg * 4;
            *(uint32_t*)p           = hi;
            *(uint32_t*)(p + 16384) = mid;
        }
    }
    __syncthreads();

    int pb = 0;
    for (int tile = blockIdx.x; tile < NTILES; tile += gridDim.x, pb ^= 1) {
        const int e0 = tile * TILE;
        const int* rs  = (const int*)(sm + SM_RS) + pb * TILE;
        const int* ssn = (const int*)(sm + SM_SS) + pb * TILE;

        // ============ GEMM1 (edge chunk only): [128,64] @ W_in[64:128] ======
        float C1[2][8][4];
        #pragma unroll
        for (int a = 0; a < 2; a++)
            #pragma unroll
            for (int b = 0; b < 8; b++)
                #pragma unroll
                for (int c = 0; c < 4; c++) C1[a][b][c] = 0.f;
        {
            const char* abase = sm + SM_PING + pb * 32768;
            #pragma unroll
            for (int sl = 0; sl < 4; sl++) {
                uint4 Ah[2], Am[2];
                #pragma unroll
                for (int m2 = 0; m2 < 2; m2++) {
                    int mt = (wm << 1) + m2;
                    const char* p = abase + (((mt << 2) + sl) << 9) + lane * 16;
                    Ah[m2] = *(const uint4*)p;
                    Am[m2] = *(const uint4*)(p + 16384);
                }
                #pragma unroll
                for (int j8 = 0; j8 < 8; j8++) {
                    int jg = (wn << 3) + j8;
                    uint4 B = *(const uint4*)(sm + SM_W1 + (size_t)(sl * 16 + jg) * 512 + lane * 16);
                    #pragma unroll
                    for (int m2 = 0; m2 < 2; m2++) {
                        mma_bf16(C1[m2][j8], (const uint32_t*)&Ah[m2], B.x, B.y);
                        mma_bf16(C1[m2][j8], (const uint32_t*)&Ah[m2], B.z, B.w);
                        mma_bf16(C1[m2][j8], (const uint32_t*)&Am[m2], B.x, B.y);
                    }
                }
            }
        }

        // ============ epilogue1: h = relu(C1 + P_r + P_s) -> h frags ========
        #pragma unroll
        for (int m2 = 0; m2 < 2; m2++) {
            int mt = (wm << 1) + m2;
            int r0 = (wm << 5) + (m2 << 4) + g;
            const float2* Pra = (const float2*)(g_P + (size_t)rs[r0] * 256);
            const float2* Prb = (const float2*)(g_P + (size_t)rs[r0 + 8] * 256);
            const float2* Psa = (const float2*)(g_P + (size_t)ssn[r0] * 256) + 64;
            const float2* Psb = (const float2*)(g_P + (size_t)ssn[r0 + 8] * 256) + 64;
            float2 va[8], vb[8], vc[8], vd[8];
            #pragma unroll
            for (int j8 = 0; j8 < 8; j8++) {
                int colf = ((wn << 3) + j8) * 4 + t;
                va[j8] = Pra[colf]; vb[j8] = Prb[colf];
                vc[j8] = Psa[colf]; vd[j8] = Psb[colf];
            }
            #pragma unroll
            for (int j8e = 0; j8e < 8; j8e += 2) {
                uint4 Hh, Hm;
                uint32_t* hh = (uint32_t*)&Hh;
                uint32_t* hm = (uint32_t*)&Hm;
                #pragma unroll
                for (int q = 0; q < 2; q++) {
                    int j8 = j8e + q;
                    float v0 = fmaxf(C1[m2][j8][0] + va[j8].x + vc[j8].x, 0.f);
                    float v1 = fmaxf(C1[m2][j8][1] + va[j8].y + vc[j8].y, 0.f);
                    float v2 = fmaxf(C1[m2][j8][2] + vb[j8].x + vd[j8].x, 0.f);
                    float v3 = fmaxf(C1[m2][j8][3] + vb[j8].y + vd[j8].y, 0.f);
                    split2(v0, v1, hh[q * 2],     hm[q * 2]);
                    split2(v2, v3, hh[q * 2 + 1], hm[q * 2 + 1]);
                }
                int s2 = ((wn << 3) + j8e) >> 1;
                char* p = sm + SM_AB + (((mt << 3) + s2) << 9) + lane * 16;
                *(uint4*)p           = Hh;
                *(uint4*)(p + 32768) = Hm;
            }
        }
        __syncthreads();   // S1: h frags visible

        // ---- prefetch next tile (issue LDGs before GEMM2 MMA) ----
        const int nt = tile + (int)gridDim.x;
        const bool valid = nt < NTILES;
        float2 ev[16];
        int nr = 0, nss = 0;
        if (valid) {
            const float2* ebase = (const float2*)(edges + (size_t)nt * TILE * DE);
            #pragma unroll
            for (int ii = 0; ii < 16; ii++) ev[ii] = ebase[tid + ii * THREADS];
            if (tid < TILE) {
                int ge = nt * TILE + tid, b = ge >> 16;
                nr  = receivers[ge] + (b << 13);
                nss = senders[ge]   + (b << 13);
            }
        }

        // ============ GEMM2: h[128,128] @ W_out -> C2[128,64] ===============
        float C2[2][4][4];
        #pragma unroll
        for (int a = 0; a < 2; a++)
            #pragma unroll
            for (int b = 0; b < 4; b++)
                #pragma unroll
                for (int c = 0; c < 4; c++) C2[a][b][c] = 0.f;
        #pragma unroll
        for (int s2 = 0; s2 < 8; s2++) {
            uint4 Ah[2], Am[2];
            #pragma unroll
            for (int m2 = 0; m2 < 2; m2++) {
                int mt = (wm << 1) + m2;
                const char* p = sm + SM_AB + (((mt << 3) + s2) << 9) + lane * 16;
                Ah[m2] = *(const uint4*)p;
                Am[m2] = *(const uint4*)(p + 32768);
            }
            #pragma unroll
            for (int j4 = 0; j4 < 4; j4++) {
                int jg = (wn << 2) + j4;
                uint4 B = *(const uint4*)(sm + SM_W2 + (size_t)(s2 * 8 + jg) * 512 + lane * 16);
                #pragma unroll
                for (int m2 = 0; m2 < 2; m2++) {
                    mma_bf16(C2[m2][j4], (const uint32_t*)&Ah[m2], B.x, B.y);
                    mma_bf16(C2[m2][j4], (const uint32_t*)&Ah[m2], B.z, B.w);
                    mma_bf16(C2[m2][j4], (const uint32_t*)&Am[m2], B.x, B.y);
                }
            }
        }

        // ---- store prefetched chunk + indices into alternate buffers ----
        if (valid) {
            #pragma unroll
            for (int ii = 0; ii < 16; ii++) {
                int idx = tid + ii * THREADS;
                uint32_t hi, mid;
                split2(ev[ii].x, ev[ii].y, hi, mid);
                int e = idx >> 5, j = idx & 31;
                int mt = e >> 4, sl = j >> 3;
                int ln = ((e & 7) << 2) | (j & 3);
                int rg = ((e >> 3) & 1) | (((j >> 2) & 1) << 1);
                char* p = sm + SM_PING + (pb ^ 1) * 32768 + (((mt << 2) + sl) << 9) + ln * 16 + rg * 4;
                *(uint32_t*)p           = hi;
                *(uint32_t*)(p + 16384) = mid;
            }
            if (tid < TILE) {
                ((int*)(sm + SM_RS))[(pb ^ 1) * TILE + tid] = nr;
                ((int*)(sm + SM_SS))[(pb ^ 1) * TILE + tid] = nss;
                atomicAdd(&g_cnts[nr], 1.0f);
            }
        }
        __syncthreads();   // S2: GEMM2 reads done; prefetch stores visible

        // ============ epilogue2: e_new -> atomics + e frags =================
        #pragma unroll
        for (int m2 = 0; m2 < 2; m2++) {
            int r0 = (wm << 5) + (m2 << 4) + g;
            int n0 = rs[r0], n1 = rs[r0 + 8];
            int mt = (wm << 1) + m2;
            #pragma unroll
            for (int j4e = 0; j4e < 4; j4e += 2) {
                uint4 Eh, Em;
                uint32_t* eh = (uint32_t*)&Eh;
                uint32_t* em = (uint32_t*)&Em;
                #pragma unroll
                for (int q = 0; q < 2; q++) {
                    int j4 = j4e + q;
                    int col = (((wn << 2) + j4) << 3) + (t << 1);
                    float v0 = fmaxf(C2[m2][j4][0] + bo[col],     0.f);
                    float v1 = fmaxf(C2[m2][j4][1] + bo[col + 1], 0.f);
                    float v2 = fmaxf(C2[m2][j4][2] + bo[col],     0.f);
                    float v3 = fmaxf(C2[m2][j4][3] + bo[col + 1], 0.f);
                    atomicAdd(&g_sums[(size_t)n0 * DN + col],     v0);
                    atomicAdd(&g_sums[(size_t)n0 * DN + col + 1], v1);
                    atomicAdd(&g_sums[(size_t)n1 * DN + col],     v2);
                    atomicAdd(&g_sums[(size_t)n1 * DN + col + 1], v3);
                    split2(v0, v1, eh[q * 2],     em[q * 2]);
                    split2(v2, v3, eh[q * 2 + 1], em[q * 2 + 1]);
                }
                int s3 = ((wn << 2) + j4e) >> 1;
                char* p = sm + SM_AB + (((mt << 2) + s3) << 9) + lane * 16;
                *(uint4*)p           = Eh;
                *(uint4*)(p + 16384) = Em;
            }
        }
        __syncthreads();   // S3: e frags visible

        // ============ GEMM3: e[128,64] @ W_edge -> C3 =======================
        float C3[2][4][4];
        #pragma unroll
        for (int a = 0; a < 2; a++)
            #pragma unroll
            for (int b = 0; b < 4; b++)
                #pragma unroll
                for (int c = 0; c < 4; c++) C3[a][b][c] = 0.f;
        #pragma unroll
        for (int s3 = 0; s3 < 4; s3++) {
            uint4 Ah[2], Am[2];
            #pragma unroll
            for (int m2 = 0; m2 < 2; m2++) {
                int mt = (wm << 1) + m2;
                const char* p = sm + SM_AB + (((mt << 2) + s3) << 9) + lane * 16;
                Ah[m2] = *(const uint4*)p;
                Am[m2] = *(const uint4*)(p + 16384);
            }
            #pragma unroll
            for (int j4 = 0; j4 < 4; j4++) {
                int jg = (wn << 2) + j4;
                uint4 B = *(const uint4*)(sm + SM_W3 + (size_t)(s3 * 8 + jg) * 512 + lane * 16);
                #pragma unroll
                for (int m2 = 0; m2 < 2; m2++) {
                    mma_bf16(C3[m2][j4], (const uint32_t*)&Ah[m2], B.x, B.y);
                    mma_bf16(C3[m2][j4], (const uint32_t*)&Ah[m2], B.z, B.w);
                    mma_bf16(C3[m2][j4], (const uint32_t*)&Am[m2], B.x, B.y);
                }
            }
        }
        __syncthreads();   // S4: GEMM3 reads done before next tile's AB writes

        // ============ epilogue3: edges_out ==================================
        #pragma unroll
        for (int m2 = 0; m2 < 2; m2++) {
            int row = e0 + (wm << 5) + (m2 << 4) + g;
            #pragma unroll
            for (int j4 = 0; j4 < 4; j4++) {
                int col = (((wn << 2) + j4) << 3) + (t << 1);
                float2 va, vb;
                va.x = fmaxf(C3[m2][j4][0] + be[col],     0.f);
                va.y = fmaxf(C3[m2][j4][1] + be[col + 1], 0.f);
                vb.x = fmaxf(C3[m2][j4][2] + be[col],     0.f);
                vb.y = fmaxf(C3[m2][j4][3] + be[col + 1], 0.f);
                *(float2*)(out_edges + (size_t)row       * DE + col) = va;
                *(float2*)(out_edges + (size_t)(row + 8) * DE + col) = vb;
            }
        }
    }
}

// ---------------------------------------------------------------------------
__global__ void finalize_kernel(float* __restrict__ out_nodes) {
    int i = blockIdx.x * blockDim.x + threadIdx.x;
    if (i < BN * DN) {
        float c = g_cnts[i >> 6];
        out_nodes[i] = (c > 0.f) ? (g_sums[i] / c) : 0.f;
    }
}

__global__ void sr_kernel(const int* __restrict__ s, const int* __restrict__ r,
                          float* __restrict__ os, float* __restrict__ orr) {
    int i = blockIdx.x * blockDim.x + threadIdx.x;
    if (i < BE) {
        os[i]  = (float)s[i];
        orr[i] = (float)r[i];
    }
}

// ---------------------------------------------------------------------------
extern "C" void kernel_launch(void* const* d_in, const int* in_sizes, int n_in,
                              void* d_out, int out_size) {
    const float* nodes     = (const float*)d_in[0];
    const float* edges     = (const float*)d_in[1];
    const int*   senders   = (const int*)  d_in[2];
    const int*   receivers = (const int*)  d_in[3];
    const float* W_in      = (const float*)d_in[4];
    const float* b_in      = (const float*)d_in[5];
    const float* W_out     = (const float*)d_in[6];
    const float* b_out     = (const float*)d_in[7];
    const float* W_edge    = (const float*)d_in[8];
    const float* b_edge    = (const float*)d_in[9];

    float* out       = (float*)d_out;
    float* out_nodes = out;
    float* out_edges = out_nodes + (size_t)BN * DN;
    float* out_s     = out_edges + (size_t)BE * DE;
    float* out_r     = out_s + BE;

    cudaFuncSetAttribute(pnode_kernel,
                         cudaFuncAttributeMaxDynamicSharedMemorySize, PSM_TOTAL);
    cudaFuncSetAttribute(edge_kernel,
                         cudaFuncAttributeMaxDynamicSharedMemorySize, SMEM_TOTAL);

    int sm_count = 148;
    cudaDeviceGetAttribute(&sm_count, cudaDevAttrMultiProcessorCount, 0);

    zero_kernel<<<1024, 256>>>();
    pnode_kernel<<<BN / 128, THREADS, PSM_TOTAL>>>(nodes, W_in, b_in);
    edge_kernel<<<sm_count, THREADS, SMEM_TOTAL>>>(
        edges, senders, receivers,
        W_in, W_out, b_out, W_edge, b_edge, out_edges);
    finalize_kernel<<<(BN * DN + 255) / 256, 256>>>(out_nodes);
    sr_kernel<<<(BE + 255) / 256, 256>>>(senders, receivers, out_s, out_r);
}

// round 5
// speedup vs baseline: 3.9071x; 1.0293x over previous
#include <cuda_runtime.h>
#include <cuda_bf16.h>
#include <cstdint>

// Problem constants
#define NNODES 8192
#define DN  64
#define DE  64
#define IUU 128
#define BE  524288
#define BN  65536
#define TILE 128
#define NTILES (BE / TILE)     // 4096
#define THREADS 512

// Device-global scratch (no allocation allowed)
__device__ float g_sums[(size_t)BN * DN];    // 16 MB
__device__ float g_cnts[BN];
__device__ float g_P[(size_t)BN * 256];      // 64 MB: [P_r(128) || P_s(128)] per node

// ---------------- edge-kernel smem layout (bytes) ----------------
#define SM_RS   0                        // 2 x 128 ints (double buffered)
#define SM_SS   1024                     // 2 x 128 ints
#define SM_BO   2048                     // 64 f
#define SM_BE2  2304                     // 64 f
#define SM_W1   4096                     // edge part of W_in: 4s*16j*512 = 32768
#define SM_W2   36864                    // 8s*8j*512 = 32768
#define SM_W3   69632                    // 4s*8j*512 = 16384
#define SM_AB   86016                    // h frags 64K (hi + mid@+32768); e frags overlay 32K (mid@+16384)
#define SM_PING 151552                   // 2 x 32768 edge-chunk frag buffers (hi + mid@+16384)
#define SMEM_TOTAL 217088

// ---------------- pnode-kernel smem layout ----------------
#define PSM_W   0                        // 4s*32j*512 = 65536
#define PSM_A   65536                    // 32768 (hi + mid@+16384)
#define PSM_B   98304                    // 128 f bias
#define PSM_TOTAL 98816
#define PTHREADS 256

// ---------------------------------------------------------------------------
__device__ __forceinline__ void mma_bf16(float* c, const uint32_t* a,
                                         uint32_t b0, uint32_t b1) {
    asm volatile(
        "mma.sync.aligned.m16n8k16.row.col.f32.bf16.bf16.f32 "
        "{%0,%1,%2,%3},{%4,%5,%6,%7},{%8,%9},{%0,%1,%2,%3};"
        : "+f"(c[0]), "+f"(c[1]), "+f"(c[2]), "+f"(c[3])
        : "r"(a[0]), "r"(a[1]), "r"(a[2]), "r"(a[3]), "r"(b0), "r"(b1));
}

__device__ __forceinline__ void split2(float x, float y, uint32_t& hi, uint32_t& mid) {
    __nv_bfloat162 h = __floats2bfloat162_rn(x, y);
    float rx = x - __bfloat162float(h.x);
    float ry = y - __bfloat162float(h.y);
    __nv_bfloat162 m = __floats2bfloat162_rn(rx, ry);
    hi  = *reinterpret_cast<uint32_t*>(&h);
    mid = *reinterpret_cast<uint32_t*>(&m);
}

// Weights -> B-frag layout, hi/mid interleaved per 16B: {hi0,hi1,mid0,mid1}.
// W is [K, Nw] row-major; frag (s,j): n = 8j+g, reg r: k = 16s+2t+8r.
__device__ __forceinline__ void load_wfrag(const float* __restrict__ W, int K, int NT,
                                           char* dst, int wid, int lane, int nwarps) {
    const int g = lane >> 2, t = lane & 3;
    const int Nw = NT * 8;
    const int SF = K / 16;
    for (int f = wid; f < SF * NT; f += nwarps) {
        int s = f / NT, j = f - s * NT;
        int n = j * 8 + g;
        uint4 v;
        uint32_t* vp = (uint32_t*)&v;
        #pragma unroll
        for (int r = 0; r < 2; r++) {
            int k = s * 16 + 2 * t + 8 * r;
            split2(W[(size_t)k * Nw + n], W[(size_t)(k + 1) * Nw + n], vp[r], vp[2 + r]);
        }
        *(uint4*)(dst + (size_t)f * 512 + lane * 16) = v;
    }
}

// ---------------------------------------------------------------------------
__global__ void zero_kernel() {
    int stride = gridDim.x * blockDim.x;
    int i = blockIdx.x * blockDim.x + threadIdx.x;
    float4 z = make_float4(0.f, 0.f, 0.f, 0.f);
    for (int j = i; j < BN * DN / 4; j += stride) ((float4*)g_sums)[j] = z;
    for (int j = i; j < BN / 4; j += stride)      ((float4*)g_cnts)[j] = z;
}

// ---------------------------------------------------------------------------
// P[n][0:128)   = nodes[n] @ W_in[0:64]   + b_in   (receiver part)
// P[n][128:256) = nodes[n] @ W_in[128:192]         (sender part)
__global__ __launch_bounds__(PTHREADS, 1)
void pnode_kernel(const float* __restrict__ nodes,
                  const float* __restrict__ W_in,
                  const float* __restrict__ b_in)
{
    extern __shared__ char sm[];
    const int tid  = threadIdx.x;
    const int lane = tid & 31;
    const int wid  = tid >> 5;
    const int g = lane >> 2, t = lane & 3;
    const int wm = wid & 3;
    const int wn = wid >> 2;

    for (int f = wid; f < 4 * 32; f += (PTHREADS / 32)) {
        int s = f >> 5, j = f & 31;
        int n = j * 8 + g;
        uint4 v;
        uint32_t* vp = (uint32_t*)&v;
        #pragma unroll
        for (int r = 0; r < 2; r++) {
            int k = s * 16 + 2 * t + 8 * r;
            float x, y;
            if (n < 128) { x = W_in[(size_t)k * IUU + n];         y = W_in[(size_t)(k + 1) * IUU + n]; }
            else         { x = W_in[(size_t)(128 + k) * IUU + n - 128];
                           y = W_in[(size_t)(129 + k) * IUU + n - 128]; }
            split2(x, y, vp[r], vp[2 + r]);
        }
        *(uint4*)(sm + PSM_W + (size_t)f * 512 + lane * 16) = v;
    }
    if (tid < IUU) ((float*)(sm + PSM_B))[tid] = b_in[tid];

    const int m0 = blockIdx.x * 128;
    #pragma unroll
    for (int ii = 0; ii < 16; ii++) {
        int idx = tid + ii * PTHREADS;
        int e = idx >> 5, j = idx & 31;
        float2 v = ((const float2*)(nodes + (size_t)(m0 + e) * DN))[j];
        uint32_t hi, mid;
        split2(v.x, v.y, hi, mid);
        int mt = e >> 4, sl = j >> 3;
        int ln = ((e & 7) << 2) | (j & 3);
        int rg = ((e >> 3) & 1) | (((j >> 2) & 1) << 1);
        char* p = sm + PSM_A + (((mt << 2) + sl) << 9) + ln * 16 + rg * 4;
        *(uint32_t*)p           = hi;
        *(uint32_t*)(p + 16384) = mid;
    }
    __syncthreads();

    const float* bi = (const float*)(sm + PSM_B);
    #pragma unroll
    for (int np = 0; np < 2; np++) {
        float C[2][8][4];
        #pragma unroll
        for (int a = 0; a < 2; a++)
            #pragma unroll
            for (int b = 0; b < 8; b++)
                #pragma unroll
                for (int c = 0; c < 4; c++) C[a][b][c] = 0.f;
        #pragma unroll
        for (int sl = 0; sl < 4; sl++) {
            uint4 Ah[2], Am[2];
            #pragma unroll
            for (int m2 = 0; m2 < 2; m2++) {
                int mt = (wm << 1) + m2;
                const char* p = sm + PSM_A + (((mt << 2) + sl) << 9) + lane * 16;
                Ah[m2] = *(const uint4*)p;
                Am[m2] = *(const uint4*)(p + 16384);
            }
            #pragma unroll
            for (int j8 = 0; j8 < 8; j8++) {
                int jg = wn * 16 + np * 8 + j8;
                uint4 B = *(const uint4*)(sm + PSM_W + (size_t)(sl * 32 + jg) * 512 + lane * 16);
                #pragma unroll
                for (int m2 = 0; m2 < 2; m2++) {
                    mma_bf16(C[m2][j8], (const uint32_t*)&Ah[m2], B.x, B.y);
                    mma_bf16(C[m2][j8], (const uint32_t*)&Ah[m2], B.z, B.w);
                    mma_bf16(C[m2][j8], (const uint32_t*)&Am[m2], B.x, B.y);
                }
            }
        }
        #pragma unroll
        for (int m2 = 0; m2 < 2; m2++) {
            int row = m0 + wm * 32 + m2 * 16 + g;
            #pragma unroll
            for (int j8 = 0; j8 < 8; j8++) {
                int col = (wn * 16 + np * 8 + j8) * 8 + t * 2;
                float bx = (col < 128) ? bi[col]     : 0.f;
                float by = (col < 128) ? bi[col + 1] : 0.f;
                float2 va, vb;
                va.x = C[m2][j8][0] + bx; va.y = C[m2][j8][1] + by;
                vb.x = C[m2][j8][2] + bx; vb.y = C[m2][j8][3] + by;
                *(float2*)(g_P + (size_t)row * 256 + col)       = va;
                *(float2*)(g_P + (size_t)(row + 8) * 256 + col) = vb;
            }
        }
    }
}

// ---------------------------------------------------------------------------
__global__ __launch_bounds__(THREADS, 1)
void edge_kernel(const float* __restrict__ edges,
                 const int*   __restrict__ senders,
                 const int*   __restrict__ receivers,
                 const float* __restrict__ W_in,
                 const float* __restrict__ W_out, const float* __restrict__ b_out,
                 const float* __restrict__ W_edge,const float* __restrict__ b_edge,
                 float* __restrict__ out_edges)
{
    extern __shared__ char sm[];
    const int tid  = threadIdx.x;
    const int lane = tid & 31;
    const int wid  = tid >> 5;
    const int g = lane >> 2, t = lane & 3;
    const int wm = wid & 7;                 // M band: rows 16*wm
    const int wn = wid >> 3;                // N half

    // one-time: weights (W_in edge part = rows 64..127), biases
    load_wfrag(W_in + 64 * IUU, 64, 16, sm + SM_W1, wid, lane, THREADS / 32);
    load_wfrag(W_out, 128, 8, sm + SM_W2, wid, lane, THREADS / 32);
    load_wfrag(W_edge, 64, 8, sm + SM_W3, wid, lane, THREADS / 32);
    if (tid < DN) ((float*)(sm + SM_BO))[tid]  = b_out[tid];
    if (tid < DE) ((float*)(sm + SM_BE2))[tid] = b_edge[tid];

    const float* bo = (const float*)(sm + SM_BO);
    const float* be = (const float*)(sm + SM_BE2);

    // prologue: tile0 indices + edge chunk into buffer 0
    {
        int tile0 = blockIdx.x;
        if (tid < TILE) {
            int ge = tile0 * TILE + tid, b = ge >> 16;
            int nr = receivers[ge] + (b << 13);
            ((int*)(sm + SM_RS))[tid] = nr;
            ((int*)(sm + SM_SS))[tid] = senders[ge] + (b << 13);
            atomicAdd(&g_cnts[nr], 1.0f);
        }
        const float2* ebase = (const float2*)(edges + (size_t)tile0 * TILE * DE);
        #pragma unroll
        for (int ii = 0; ii < 8; ii++) {
            int idx = tid + ii * THREADS;
            float2 v = ebase[idx];
            uint32_t hi, mid;
            split2(v.x, v.y, hi, mid);
            int e = idx >> 5, j = idx & 31;
            int mt = e >> 4, sl = j >> 3;
            int ln = ((e & 7) << 2) | (j & 3);
            int rg = ((e >> 3) & 1) | (((j >> 2) & 1) << 1);
            char* p = sm + SM_PING + (((mt << 2) + sl) << 9) + ln * 16 + rg * 4;
            *(uint32_t*)p           = hi;
            *(uint32_t*)(p + 16384) = mid;
        }
    }
    __syncthreads();

    int pb = 0;
    for (int tile = blockIdx.x; tile < NTILES; tile += gridDim.x, pb ^= 1) {
        const int e0 = tile * TILE;
        const int* rs  = (const int*)(sm + SM_RS) + pb * TILE;
        const int* ssn = (const int*)(sm + SM_SS) + pb * TILE;

        // ---- prefetch next tile (issue LDGs before GEMM1) ----
        const int nt = tile + (int)gridDim.x;
        const bool valid = nt < NTILES;
        float2 ev[8];
        int nr = 0, nss = 0;
        if (valid) {
            const float2* ebase = (const float2*)(edges + (size_t)nt * TILE * DE);
            #pragma unroll
            for (int ii = 0; ii < 8; ii++) ev[ii] = ebase[tid + ii * THREADS];
            if (tid < TILE) {
                int ge = nt * TILE + tid, b = ge >> 16;
                nr  = receivers[ge] + (b << 13);
                nss = senders[ge]   + (b << 13);
            }
        }

        // ============ GEMM1 (edge chunk): [128,64] @ W_in[64:128] ==========
        float C1[8][4];
        #pragma unroll
        for (int b = 0; b < 8; b++)
            #pragma unroll
            for (int c = 0; c < 4; c++) C1[b][c] = 0.f;
        {
            const char* abase = sm + SM_PING + pb * 32768;
            #pragma unroll
            for (int sl = 0; sl < 4; sl++) {
                const char* p = abase + (((wm << 2) + sl) << 9) + lane * 16;
                uint4 Ah = *(const uint4*)p;
                uint4 Am = *(const uint4*)(p + 16384);
                #pragma unroll
                for (int j8 = 0; j8 < 8; j8++) {
                    int jg = (wn << 3) + j8;
                    uint4 B = *(const uint4*)(sm + SM_W1 + (size_t)(sl * 16 + jg) * 512 + lane * 16);
                    mma_bf16(C1[j8], (const uint32_t*)&Ah, B.x, B.y);
                    mma_bf16(C1[j8], (const uint32_t*)&Ah, B.z, B.w);
                    mma_bf16(C1[j8], (const uint32_t*)&Am, B.x, B.y);
                }
            }
        }

        // ---- store prefetched chunk + indices into alternate buffers ----
        if (valid) {
            #pragma unroll
            for (int ii = 0; ii < 8; ii++) {
                int idx = tid + ii * THREADS;
                uint32_t hi, mid;
                split2(ev[ii].x, ev[ii].y, hi, mid);
                int e = idx >> 5, j = idx & 31;
                int mt = e >> 4, sl = j >> 3;
                int ln = ((e & 7) << 2) | (j & 3);
                int rg = ((e >> 3) & 1) | (((j >> 2) & 1) << 1);
                char* p = sm + SM_PING + (pb ^ 1) * 32768 + (((mt << 2) + sl) << 9) + ln * 16 + rg * 4;
                *(uint32_t*)p           = hi;
                *(uint32_t*)(p + 16384) = mid;
            }
            if (tid < TILE) {
                ((int*)(sm + SM_RS))[(pb ^ 1) * TILE + tid] = nr;
                ((int*)(sm + SM_SS))[(pb ^ 1) * TILE + tid] = nss;
                atomicAdd(&g_cnts[nr], 1.0f);
            }
        }

        // ============ epilogue1: h = relu(C1 + P_r + P_s) -> h frags ========
        {
            int r0 = (wm << 4) + g;
            const float2* Pra = (const float2*)(g_P + (size_t)rs[r0] * 256);
            const float2* Prb = (const float2*)(g_P + (size_t)rs[r0 + 8] * 256);
            const float2* Psa = (const float2*)(g_P + (size_t)ssn[r0] * 256) + 64;
            const float2* Psb = (const float2*)(g_P + (size_t)ssn[r0 + 8] * 256) + 64;
            #pragma unroll
            for (int jj = 0; jj < 2; jj++) {
                float2 va[4], vb[4], vc[4], vd[4];
                #pragma unroll
                for (int u = 0; u < 4; u++) {
                    int colf = ((wn << 3) + jj * 4 + u) * 4 + t;
                    va[u] = Pra[colf]; vb[u] = Prb[colf];
                    vc[u] = Psa[colf]; vd[u] = Psb[colf];
                }
                #pragma unroll
                for (int j8e = 0; j8e < 4; j8e += 2) {
                    uint4 Hh, Hm;
                    uint32_t* hh = (uint32_t*)&Hh;
                    uint32_t* hm = (uint32_t*)&Hm;
                    #pragma unroll
                    for (int q = 0; q < 2; q++) {
                        int u = j8e + q;
                        int j8 = jj * 4 + u;
                        float v0 = fmaxf(C1[j8][0] + va[u].x + vc[u].x, 0.f);
                        float v1 = fmaxf(C1[j8][1] + va[u].y + vc[u].y, 0.f);
                        float v2 = fmaxf(C1[j8][2] + vb[u].x + vd[u].x, 0.f);
                        float v3 = fmaxf(C1[j8][3] + vb[u].y + vd[u].y, 0.f);
                        split2(v0, v1, hh[q * 2],     hm[q * 2]);
                        split2(v2, v3, hh[q * 2 + 1], hm[q * 2 + 1]);
                    }
                    int s2 = ((wn << 3) + jj * 4 + j8e) >> 1;
                    char* p = sm + SM_AB + (((wm << 3) + s2) << 9) + lane * 16;
                    *(uint4*)p           = Hh;
                    *(uint4*)(p + 32768) = Hm;
                }
            }
        }
        __syncthreads();   // S1: h frags + prefetch stores visible

        // ============ GEMM2: h[128,128] @ W_out -> C2[128,64] ===============
        float C2[4][4];
        #pragma unroll
        for (int b = 0; b < 4; b++)
            #pragma unroll
            for (int c = 0; c < 4; c++) C2[b][c] = 0.f;
        #pragma unroll
        for (int s2 = 0; s2 < 8; s2++) {
            const char* p = sm + SM_AB + (((wm << 3) + s2) << 9) + lane * 16;
            uint4 Ah = *(const uint4*)p;
            uint4 Am = *(const uint4*)(p + 32768);
            #pragma unroll
            for (int j4 = 0; j4 < 4; j4++) {
                int jg = (wn << 2) + j4;
                uint4 B = *(const uint4*)(sm + SM_W2 + (size_t)(s2 * 8 + jg) * 512 + lane * 16);
                mma_bf16(C2[j4], (const uint32_t*)&Ah, B.x, B.y);
                mma_bf16(C2[j4], (const uint32_t*)&Ah, B.z, B.w);
                mma_bf16(C2[j4], (const uint32_t*)&Am, B.x, B.y);
            }
        }
        __syncthreads();   // S2: GEMM2 reads of AB done

        // ============ epilogue2: e_new -> atomics + e frags =================
        {
            int r0 = (wm << 4) + g;
            int n0 = rs[r0], n1 = rs[r0 + 8];
            #pragma unroll
            for (int j4e = 0; j4e < 4; j4e += 2) {
                uint4 Eh, Em;
                uint32_t* eh = (uint32_t*)&Eh;
                uint32_t* em = (uint32_t*)&Em;
                #pragma unroll
                for (int q = 0; q < 2; q++) {
                    int j4 = j4e + q;
                    int col = (((wn << 2) + j4) << 3) + (t << 1);
                    float v0 = fmaxf(C2[j4][0] + bo[col],     0.f);
                    float v1 = fmaxf(C2[j4][1] + bo[col + 1], 0.f);
                    float v2 = fmaxf(C2[j4][2] + bo[col],     0.f);
                    float v3 = fmaxf(C2[j4][3] + bo[col + 1], 0.f);
                    atomicAdd(&g_sums[(size_t)n0 * DN + col],     v0);
                    atomicAdd(&g_sums[(size_t)n0 * DN + col + 1], v1);
                    atomicAdd(&g_sums[(size_t)n1 * DN + col],     v2);
                    atomicAdd(&g_sums[(size_t)n1 * DN + col + 1], v3);
                    split2(v0, v1, eh[q * 2],     em[q * 2]);
                    split2(v2, v3, eh[q * 2 + 1], em[q * 2 + 1]);
                }
                int s3 = ((wn << 2) + j4e) >> 1;
                char* p = sm + SM_AB + (((wm << 2) + s3) << 9) + lane * 16;
                *(uint4*)p           = Eh;
                *(uint4*)(p + 16384) = Em;
            }
        }
        __syncthreads();   // S3: e frags visible

        // ============ GEMM3: e[128,64] @ W_edge -> C3 =======================
        float C3[4][4];
        #pragma unroll
        for (int b = 0; b < 4; b++)
            #pragma unroll
            for (int c = 0; c < 4; c++) C3[b][c] = 0.f;
        #pragma unroll
        for (int s3 = 0; s3 < 4; s3++) {
            const char* p = sm + SM_AB + (((wm << 2) + s3) << 9) + lane * 16;
            uint4 Ah = *(const uint4*)p;
            uint4 Am = *(const uint4*)(p + 16384);
            #pragma unroll
            for (int j4 = 0; j4 < 4; j4++) {
                int jg = (wn << 2) + j4;
                uint4 B = *(const uint4*)(sm + SM_W3 + (size_t)(s3 * 8 + jg) * 512 + lane * 16);
                mma_bf16(C3[j4], (const uint32_t*)&Ah, B.x, B.y);
                mma_bf16(C3[j4], (const uint32_t*)&Ah, B.z, B.w);
                mma_bf16(C3[j4], (const uint32_t*)&Am, B.x, B.y);
            }
        }
        __syncthreads();   // S4: GEMM3 reads done before next tile's AB writes

        // ============ epilogue3: edges_out ==================================
        {
            int row = e0 + (wm << 4) + g;
            #pragma unroll
            for (int j4 = 0; j4 < 4; j4++) {
                int col = (((wn << 2) + j4) << 3) + (t << 1);
                float2 va, vb;
                va.x = fmaxf(C3[j4][0] + be[col],     0.f);
                va.y = fmaxf(C3[j4][1] + be[col + 1], 0.f);
                vb.x = fmaxf(C3[j4][2] + be[col],     0.f);
                vb.y = fmaxf(C3[j4][3] + be[col + 1], 0.f);
                *(float2*)(out_edges + (size_t)row       * DE + col) = va;
                *(float2*)(out_edges + (size_t)(row + 8) * DE + col) = vb;
            }
        }
    }
}

// ---------------------------------------------------------------------------
__global__ void finalize_kernel(float* __restrict__ out_nodes) {
    int i = blockIdx.x * blockDim.x + threadIdx.x;   // over BN*DN/4
    if (i < BN * (DN / 4)) {
        float c = g_cnts[i >> 4];
        float inv = (c > 0.f) ? (1.0f / c) : 0.f;
        float4 s = ((const float4*)g_sums)[i];
        s.x *= inv; s.y *= inv; s.z *= inv; s.w *= inv;
        ((float4*)out_nodes)[i] = s;
    }
}

__global__ void sr_kernel(const int* __restrict__ s, const int* __restrict__ r,
                          float* __restrict__ os, float* __restrict__ orr) {
    int i = blockIdx.x * blockDim.x + threadIdx.x;   // over BE/4
    if (i < BE / 4) {
        int4 sv = ((const int4*)s)[i];
        int4 rv = ((const int4*)r)[i];
        float4 so, ro;
        so.x = (float)sv.x; so.y = (float)sv.y; so.z = (float)sv.z; so.w = (float)sv.w;
        ro.x = (float)rv.x; ro.y = (float)rv.y; ro.z = (float)rv.z; ro.w = (float)rv.w;
        ((float4*)os)[i]  = so;
        ((float4*)orr)[i] = ro;
    }
}

// ---------------------------------------------------------------------------
extern "C" void kernel_launch(void* const* d_in, const int* in_sizes, int n_in,
                              void* d_out, int out_size) {
    const float* nodes     = (const float*)d_in[0];
    const float* edges     = (const float*)d_in[1];
    const int*   senders   = (const int*)  d_in[2];
    const int*   receivers = (const int*)  d_in[3];
    const float* W_in      = (const float*)d_in[4];
    const float* b_in      = (const float*)d_in[5];
    const float* W_out     = (const float*)d_in[6];
    const float* b_out     = (const float*)d_in[7];
    const float* W_edge    = (const float*)d_in[8];
    const float* b_edge    = (const float*)d_in[9];

    float* out       = (float*)d_out;
    float* out_nodes = out;
    float* out_edges = out_nodes + (size_t)BN * DN;
    float* out_s     = out_edges + (size_t)BE * DE;
    float* out_r     = out_s + BE;

    cudaFuncSetAttribute(pnode_kernel,
                         cudaFuncAttributeMaxDynamicSharedMemorySize, PSM_TOTAL);
    cudaFuncSetAttribute(edge_kernel,
                         cudaFuncAttributeMaxDynamicSharedMemorySize, SMEM_TOTAL);

    int sm_count = 148;
    cudaDeviceGetAttribute(&sm_count, cudaDevAttrMultiProcessorCount, 0);

    zero_kernel<<<2048, 256>>>();
    pnode_kernel<<<BN / 128, PTHREADS, PSM_TOTAL>>>(nodes, W_in, b_in);
    edge_kernel<<<sm_count, THREADS, SMEM_TOTAL>>>(
        edges, senders, receivers,
        W_in, W_out, b_out, W_edge, b_edge, out_edges);
    finalize_kernel<<<(BN * DN / 4 + 255) / 256, 256>>>(out_nodes);
    sr_kernel<<<(BE / 4 + 255) / 256, 256>>>(senders, receivers, out_s, out_r);
}

// round 6
// speedup vs baseline: 5.0601x; 1.2951x over previous
#include <cuda_runtime.h>
#include <cuda_bf16.h>
#include <cuda_fp16.h>
#include <cstdint>

// Problem constants
#define NNODES 8192
#define DN  64
#define DE  64
#define IUU 128
#define BE  524288
#define BN  65536
#define TILE 128
#define NTILES (BE / TILE)     // 4096
#define THREADS 512

#define INV1024 9.765625e-4f

// Device-global scratch (no allocation allowed)
__device__ float g_sums[(size_t)BN * DN];    // 16 MB
__device__ float g_cnts[BN];
__device__ float g_P[(size_t)BN * 256];      // 64 MB: [P_r(128) || P_s(128)] per node

// ---------------- edge-kernel smem layout (bytes) ----------------
#define SM_RS   0                        // 2 x 128 ints (double buffered)
#define SM_SS   1024                     // 2 x 128 ints
#define SM_BO   2048                     // 64 f
#define SM_BE2  2304                     // 64 f
#define SM_W1   4096                     // W_in edge part, hi only: 64 frags * 256 = 16384
#define SM_W2   20480                    // W_out hi+mid: 64 frags * 512 = 32768
#define SM_W3   53248                    // W_edge hi+mid: 32 frags * 512 = 16384
#define SM_AB   69632                    // h frags 32768 (fp16); e frags overlay first 16384
#define SM_PING 102400                   // 2 x 16384 edge-chunk fp16 frag buffers
#define SMEM_TOTAL 135168

// ---------------- pnode-kernel smem layout (bf16 3-term, near-exact) ------
#define PSM_W   0                        // 4s*32j*512 = 65536
#define PSM_A   65536                    // 32768 (hi + mid@+16384)
#define PSM_B   98304                    // 128 f bias
#define PSM_TOTAL 98816
#define PTHREADS 256

// ---------------------------------------------------------------------------
__device__ __forceinline__ void mma_f16(float* c, const uint32_t* a,
                                        uint32_t b0, uint32_t b1) {
    asm volatile(
        "mma.sync.aligned.m16n8k16.row.col.f32.f16.f16.f32 "
        "{%0,%1,%2,%3},{%4,%5,%6,%7},{%8,%9},{%0,%1,%2,%3};"
        : "+f"(c[0]), "+f"(c[1]), "+f"(c[2]), "+f"(c[3])
        : "r"(a[0]), "r"(a[1]), "r"(a[2]), "r"(a[3]), "r"(b0), "r"(b1));
}

__device__ __forceinline__ void mma_bf16(float* c, const uint32_t* a,
                                         uint32_t b0, uint32_t b1) {
    asm volatile(
        "mma.sync.aligned.m16n8k16.row.col.f32.bf16.bf16.f32 "
        "{%0,%1,%2,%3},{%4,%5,%6,%7},{%8,%9},{%0,%1,%2,%3};"
        : "+f"(c[0]), "+f"(c[1]), "+f"(c[2]), "+f"(c[3])
        : "r"(a[0]), "r"(a[1]), "r"(a[2]), "r"(a[3]), "r"(b0), "r"(b1));
}

// fp32 pair -> packed fp16 pair
__device__ __forceinline__ uint32_t pack_h2(float x, float y) {
    __half2 h = __floats2half2_rn(x, y);
    return *reinterpret_cast<uint32_t*>(&h);
}
// fp32 pair -> fp16 hi pair + fp16 residual*1024 pair
__device__ __forceinline__ void split2h(float x, float y, uint32_t& hi, uint32_t& mid) {
    __half2 h = __floats2half2_rn(x, y);
    float rx = (x - __half2float(__low2half(h)))  * 1024.f;
    float ry = (y - __half2float(__high2half(h))) * 1024.f;
    __half2 m = __floats2half2_rn(rx, ry);
    hi  = *reinterpret_cast<uint32_t*>(&h);
    mid = *reinterpret_cast<uint32_t*>(&m);
}
// bf16 split (for pnode)
__device__ __forceinline__ void split2(float x, float y, uint32_t& hi, uint32_t& mid) {
    __nv_bfloat162 h = __floats2bfloat162_rn(x, y);
    float rx = x - __bfloat162float(h.x);
    float ry = y - __bfloat162float(h.y);
    __nv_bfloat162 m = __floats2bfloat162_rn(rx, ry);
    hi  = *reinterpret_cast<uint32_t*>(&h);
    mid = *reinterpret_cast<uint32_t*>(&m);
}

// Weights -> fp16 B-frags, hi only (uint2/lane, 256B/frag). W [K, NT*8] row-major.
__device__ __forceinline__ void load_wfrag_h(const float* __restrict__ W, int K, int NT,
                                             char* dst, int wid, int lane, int nwarps) {
    const int g = lane >> 2, t = lane & 3;
    const int Nw = NT * 8;
    const int SF = K / 16;
    for (int f = wid; f < SF * NT; f += nwarps) {
        int s = f / NT, j = f - s * NT;
        int n = j * 8 + g;
        uint2 v;
        #pragma unroll
        for (int r = 0; r < 2; r++) {
            int k = s * 16 + 2 * t + 8 * r;
            ((uint32_t*)&v)[r] = pack_h2(W[(size_t)k * Nw + n], W[(size_t)(k + 1) * Nw + n]);
        }
        *(uint2*)(dst + (size_t)f * 256 + lane * 8) = v;
    }
}
// Weights -> fp16 B-frags, hi + scaled-mid (uint4/lane, 512B/frag).
__device__ __forceinline__ void load_wfrag_hm(const float* __restrict__ W, int K, int NT,
                                              char* dst, int wid, int lane, int nwarps) {
    const int g = lane >> 2, t = lane & 3;
    const int Nw = NT * 8;
    const int SF = K / 16;
    for (int f = wid; f < SF * NT; f += nwarps) {
        int s = f / NT, j = f - s * NT;
        int n = j * 8 + g;
        uint4 v;
        uint32_t* vp = (uint32_t*)&v;
        #pragma unroll
        for (int r = 0; r < 2; r++) {
            int k = s * 16 + 2 * t + 8 * r;
            split2h(W[(size_t)k * Nw + n], W[(size_t)(k + 1) * Nw + n], vp[r], vp[2 + r]);
        }
        *(uint4*)(dst + (size_t)f * 512 + lane * 16) = v;
    }
}

// ---------------------------------------------------------------------------
__global__ void zero_kernel() {
    int stride = gridDim.x * blockDim.x;
    int i = blockIdx.x * blockDim.x + threadIdx.x;
    float4 z = make_float4(0.f, 0.f, 0.f, 0.f);
    for (int j = i; j < BN * DN / 4; j += stride) ((float4*)g_sums)[j] = z;
    for (int j = i; j < BN / 4; j += stride)      ((float4*)g_cnts)[j] = z;
}

// ---------------------------------------------------------------------------
// P[n][0:128)   = nodes[n] @ W_in[0:64]   + b_in
// P[n][128:256) = nodes[n] @ W_in[128:192]
__global__ __launch_bounds__(PTHREADS, 1)
void pnode_kernel(const float* __restrict__ nodes,
                  const float* __restrict__ W_in,
                  const float* __restrict__ b_in)
{
    extern __shared__ char sm[];
    const int tid  = threadIdx.x;
    const int lane = tid & 31;
    const int wid  = tid >> 5;
    const int g = lane >> 2, t = lane & 3;
    const int wm = wid & 3;
    const int wn = wid >> 2;

    for (int f = wid; f < 4 * 32; f += (PTHREADS / 32)) {
        int s = f >> 5, j = f & 31;
        int n = j * 8 + g;
        uint4 v;
        uint32_t* vp = (uint32_t*)&v;
        #pragma unroll
        for (int r = 0; r < 2; r++) {
            int k = s * 16 + 2 * t + 8 * r;
            float x, y;
            if (n < 128) { x = W_in[(size_t)k * IUU + n];         y = W_in[(size_t)(k + 1) * IUU + n]; }
            else         { x = W_in[(size_t)(128 + k) * IUU + n - 128];
                           y = W_in[(size_t)(129 + k) * IUU + n - 128]; }
            split2(x, y, vp[r], vp[2 + r]);
        }
        *(uint4*)(sm + PSM_W + (size_t)f * 512 + lane * 16) = v;
    }
    if (tid < IUU) ((float*)(sm + PSM_B))[tid] = b_in[tid];

    const int m0 = blockIdx.x * 128;
    #pragma unroll
    for (int ii = 0; ii < 16; ii++) {
        int idx = tid + ii * PTHREADS;
        int e = idx >> 5, j = idx & 31;
        float2 v = ((const float2*)(nodes + (size_t)(m0 + e) * DN))[j];
        uint32_t hi, mid;
        split2(v.x, v.y, hi, mid);
        int mt = e >> 4, sl = j >> 3;
        int ln = ((e & 7) << 2) | (j & 3);
        int rg = ((e >> 3) & 1) | (((j >> 2) & 1) << 1);
        char* p = sm + PSM_A + (((mt << 2) + sl) << 9) + ln * 16 + rg * 4;
        *(uint32_t*)p           = hi;
        *(uint32_t*)(p + 16384) = mid;
    }
    __syncthreads();

    const float* bi = (const float*)(sm + PSM_B);
    #pragma unroll
    for (int np = 0; np < 2; np++) {
        float C[2][8][4];
        #pragma unroll
        for (int a = 0; a < 2; a++)
            #pragma unroll
            for (int b = 0; b < 8; b++)
                #pragma unroll
                for (int c = 0; c < 4; c++) C[a][b][c] = 0.f;
        #pragma unroll
        for (int sl = 0; sl < 4; sl++) {
            uint4 Ah[2], Am[2];
            #pragma unroll
            for (int m2 = 0; m2 < 2; m2++) {
                int mt = (wm << 1) + m2;
                const char* p = sm + PSM_A + (((mt << 2) + sl) << 9) + lane * 16;
                Ah[m2] = *(const uint4*)p;
                Am[m2] = *(const uint4*)(p + 16384);
            }
            #pragma unroll
            for (int j8 = 0; j8 < 8; j8++) {
                int jg = wn * 16 + np * 8 + j8;
                uint4 B = *(const uint4*)(sm + PSM_W + (size_t)(sl * 32 + jg) * 512 + lane * 16);
                #pragma unroll
                for (int m2 = 0; m2 < 2; m2++) {
                    mma_bf16(C[m2][j8], (const uint32_t*)&Ah[m2], B.x, B.y);
                    mma_bf16(C[m2][j8], (const uint32_t*)&Ah[m2], B.z, B.w);
                    mma_bf16(C[m2][j8], (const uint32_t*)&Am[m2], B.x, B.y);
                }
            }
        }
        #pragma unroll
        for (int m2 = 0; m2 < 2; m2++) {
            int row = m0 + wm * 32 + m2 * 16 + g;
            #pragma unroll
            for (int j8 = 0; j8 < 8; j8++) {
                int col = (wn * 16 + np * 8 + j8) * 8 + t * 2;
                float bx = (col < 128) ? bi[col]     : 0.f;
                float by = (col < 128) ? bi[col + 1] : 0.f;
                float2 va, vb;
                va.x = C[m2][j8][0] + bx; va.y = C[m2][j8][1] + by;
                vb.x = C[m2][j8][2] + bx; vb.y = C[m2][j8][3] + by;
                *(float2*)(g_P + (size_t)row * 256 + col)       = va;
                *(float2*)(g_P + (size_t)(row + 8) * 256 + col) = vb;
            }
        }
    }
}

// ---------------------------------------------------------------------------
__global__ __launch_bounds__(THREADS, 1)
void edge_kernel(const float* __restrict__ edges,
                 const int*   __restrict__ senders,
                 const int*   __restrict__ receivers,
                 const float* __restrict__ W_in,
                 const float* __restrict__ W_out, const float* __restrict__ b_out,
                 const float* __restrict__ W_edge,const float* __restrict__ b_edge,
                 float* __restrict__ out_edges)
{
    extern __shared__ char sm[];
    const int tid  = threadIdx.x;
    const int lane = tid & 31;
    const int wid  = tid >> 5;
    const int g = lane >> 2, t = lane & 3;
    const int wm = wid & 7;                 // M band: rows 16*wm
    const int wn = wid >> 3;                // N half

    // one-time weights: W1 hi-only, W2/W3 hi + scaled-mid
    load_wfrag_h (W_in + 64 * IUU, 64, 16, sm + SM_W1, wid, lane, THREADS / 32);
    load_wfrag_hm(W_out, 128, 8, sm + SM_W2, wid, lane, THREADS / 32);
    load_wfrag_hm(W_edge, 64, 8, sm + SM_W3, wid, lane, THREADS / 32);
    if (tid < DN) ((float*)(sm + SM_BO))[tid]  = b_out[tid];
    if (tid < DE) ((float*)(sm + SM_BE2))[tid] = b_edge[tid];

    const float* bo = (const float*)(sm + SM_BO);
    const float* be = (const float*)(sm + SM_BE2);

    // prologue: tile0 indices + edge chunk (fp16) into buffer 0
    {
        int tile0 = blockIdx.x;
        if (tid < TILE) {
            int ge = tile0 * TILE + tid, b = ge >> 16;
            int nr = receivers[ge] + (b << 13);
            ((int*)(sm + SM_RS))[tid] = nr;
            ((int*)(sm + SM_SS))[tid] = senders[ge] + (b << 13);
            atomicAdd(&g_cnts[nr], 1.0f);
        }
        const float2* ebase = (const float2*)(edges + (size_t)tile0 * TILE * DE);
        #pragma unroll
        for (int ii = 0; ii < 8; ii++) {
            int idx = tid + ii * THREADS;
            float2 v = ebase[idx];
            int e = idx >> 5, j = idx & 31;
            int mt = e >> 4, sl = j >> 3;
            int ln = ((e & 7) << 2) | (j & 3);
            int rg = ((e >> 3) & 1) | (((j >> 2) & 1) << 1);
            *(uint32_t*)(sm + SM_PING + (((mt << 2) + sl) << 9) + ln * 16 + rg * 4) =
                pack_h2(v.x, v.y);
        }
    }
    __syncthreads();

    int pb = 0;
    for (int tile = blockIdx.x; tile < NTILES; tile += gridDim.x, pb ^= 1) {
        const int e0 = tile * TILE;
        const int* rs  = (const int*)(sm + SM_RS) + pb * TILE;
        const int* ssn = (const int*)(sm + SM_SS) + pb * TILE;

        // ---- prefetch next tile ----
        const int nt = tile + (int)gridDim.x;
        const bool valid = nt < NTILES;
        float2 ev[8];
        int nr = 0, nss = 0;
        if (valid) {
            const float2* ebase = (const float2*)(edges + (size_t)nt * TILE * DE);
            #pragma unroll
            for (int ii = 0; ii < 8; ii++) ev[ii] = ebase[tid + ii * THREADS];
            if (tid < TILE) {
                int ge = nt * TILE + tid, b = ge >> 16;
                nr  = receivers[ge] + (b << 13);
                nss = senders[ge]   + (b << 13);
            }
        }

        // ============ GEMM1 (edge chunk, 1-term): [128,64] @ W1h ============
        float C1[8][4];
        #pragma unroll
        for (int b = 0; b < 8; b++)
            #pragma unroll
            for (int c = 0; c < 4; c++) C1[b][c] = 0.f;
        {
            const char* abase = sm + SM_PING + pb * 16384;
            #pragma unroll
            for (int sl = 0; sl < 4; sl++) {
                uint4 A = *(const uint4*)(abase + (((wm << 2) + sl) << 9) + lane * 16);
                #pragma unroll
                for (int j8 = 0; j8 < 8; j8++) {
                    int jg = (wn << 3) + j8;
                    uint2 B = *(const uint2*)(sm + SM_W1 + (size_t)(sl * 16 + jg) * 256 + lane * 8);
                    mma_f16(C1[j8], (const uint32_t*)&A, B.x, B.y);
                }
            }
        }

        // ---- store prefetched chunk + indices ----
        if (valid) {
            #pragma unroll
            for (int ii = 0; ii < 8; ii++) {
                int idx = tid + ii * THREADS;
                int e = idx >> 5, j = idx & 31;
                int mt = e >> 4, sl = j >> 3;
                int ln = ((e & 7) << 2) | (j & 3);
                int rg = ((e >> 3) & 1) | (((j >> 2) & 1) << 1);
                *(uint32_t*)(sm + SM_PING + (pb ^ 1) * 16384 +
                             (((mt << 2) + sl) << 9) + ln * 16 + rg * 4) =
                    pack_h2(ev[ii].x, ev[ii].y);
            }
            if (tid < TILE) {
                ((int*)(sm + SM_RS))[(pb ^ 1) * TILE + tid] = nr;
                ((int*)(sm + SM_SS))[(pb ^ 1) * TILE + tid] = nss;
                atomicAdd(&g_cnts[nr], 1.0f);
            }
        }

        // ============ epilogue1: h = relu(C1 + P_r + P_s) -> fp16 frags =====
        {
            int r0 = (wm << 4) + g;
            const float2* Pra = (const float2*)(g_P + (size_t)rs[r0] * 256);
            const float2* Prb = (const float2*)(g_P + (size_t)rs[r0 + 8] * 256);
            const float2* Psa = (const float2*)(g_P + (size_t)ssn[r0] * 256) + 64;
            const float2* Psb = (const float2*)(g_P + (size_t)ssn[r0 + 8] * 256) + 64;
            #pragma unroll
            for (int jj = 0; jj < 2; jj++) {
                float2 va[4], vb[4], vc[4], vd[4];
                #pragma unroll
                for (int u = 0; u < 4; u++) {
                    int colf = ((wn << 3) + jj * 4 + u) * 4 + t;
                    va[u] = Pra[colf]; vb[u] = Prb[colf];
                    vc[u] = Psa[colf]; vd[u] = Psb[colf];
                }
                #pragma unroll
                for (int j8e = 0; j8e < 4; j8e += 2) {
                    uint4 H;
                    uint32_t* hp = (uint32_t*)&H;
                    #pragma unroll
                    for (int q = 0; q < 2; q++) {
                        int u = j8e + q;
                        int j8 = jj * 4 + u;
                        float v0 = fmaxf(C1[j8][0] + va[u].x + vc[u].x, 0.f);
                        float v1 = fmaxf(C1[j8][1] + va[u].y + vc[u].y, 0.f);
                        float v2 = fmaxf(C1[j8][2] + vb[u].x + vd[u].x, 0.f);
                        float v3 = fmaxf(C1[j8][3] + vb[u].y + vd[u].y, 0.f);
                        hp[q * 2 + 0] = pack_h2(v0, v1);   // row g,   rg = 2q
                        hp[q * 2 + 1] = pack_h2(v2, v3);   // row g+8, rg = 2q+1
                    }
                    int sl2 = ((wn << 3) + jj * 4 + j8e) >> 1;
                    *(uint4*)(sm + SM_AB + (((wm << 3) + sl2) << 9) + lane * 16) = H;
                }
            }
        }
        __syncthreads();   // S1: h frags + prefetch stores visible

        // ============ GEMM2 (2-term): h[128,128] @ W_out ====================
        float C2[4][4], C2m[4][4];
        #pragma unroll
        for (int b = 0; b < 4; b++)
            #pragma unroll
            for (int c = 0; c < 4; c++) { C2[b][c] = 0.f; C2m[b][c] = 0.f; }
        #pragma unroll
        for (int s2 = 0; s2 < 8; s2++) {
            uint4 A = *(const uint4*)(sm + SM_AB + (((wm << 3) + s2) << 9) + lane * 16);
            #pragma unroll
            for (int j4 = 0; j4 < 4; j4++) {
                int jg = (wn << 2) + j4;
                uint4 B = *(const uint4*)(sm + SM_W2 + (size_t)(s2 * 8 + jg) * 512 + lane * 16);
                mma_f16(C2[j4],  (const uint32_t*)&A, B.x, B.y);
                mma_f16(C2m[j4], (const uint32_t*)&A, B.z, B.w);
            }
        }
        __syncthreads();   // S2: GEMM2 reads of AB done

        // ============ epilogue2: e_new -> atomics + fp16 e frags ============
        {
            int r0 = (wm << 4) + g;
            int n0 = rs[r0], n1 = rs[r0 + 8];
            #pragma unroll
            for (int j4e = 0; j4e < 4; j4e += 2) {
                uint4 E;
                uint32_t* ep = (uint32_t*)&E;
                #pragma unroll
                for (int q = 0; q < 2; q++) {
                    int j4 = j4e + q;
                    int col = (((wn << 2) + j4) << 3) + (t << 1);
                    float v0 = fmaxf(C2[j4][0] + C2m[j4][0] * INV1024 + bo[col],     0.f);
                    float v1 = fmaxf(C2[j4][1] + C2m[j4][1] * INV1024 + bo[col + 1], 0.f);
                    float v2 = fmaxf(C2[j4][2] + C2m[j4][2] * INV1024 + bo[col],     0.f);
                    float v3 = fmaxf(C2[j4][3] + C2m[j4][3] * INV1024 + bo[col + 1], 0.f);
                    atomicAdd(&g_sums[(size_t)n0 * DN + col],     v0);
                    atomicAdd(&g_sums[(size_t)n0 * DN + col + 1], v1);
                    atomicAdd(&g_sums[(size_t)n1 * DN + col],     v2);
                    atomicAdd(&g_sums[(size_t)n1 * DN + col + 1], v3);
                    ep[q * 2 + 0] = pack_h2(v0, v1);
                    ep[q * 2 + 1] = pack_h2(v2, v3);
                }
                int s3 = ((wn << 2) + j4e) >> 1;
                *(uint4*)(sm + SM_AB + (((wm << 2) + s3) << 9) + lane * 16) = E;
            }
        }
        __syncthreads();   // S3: e frags visible

        // ============ GEMM3 (2-term): e[128,64] @ W_edge ====================
        float C3[4][4], C3m[4][4];
        #pragma unroll
        for (int b = 0; b < 4; b++)
            #pragma unroll
            for (int c = 0; c < 4; c++) { C3[b][c] = 0.f; C3m[b][c] = 0.f; }
        #pragma unroll
        for (int s3 = 0; s3 < 4; s3++) {
            uint4 A = *(const uint4*)(sm + SM_AB + (((wm << 2) + s3) << 9) + lane * 16);
            #pragma unroll
            for (int j4 = 0; j4 < 4; j4++) {
                int jg = (wn << 2) + j4;
                uint4 B = *(const uint4*)(sm + SM_W3 + (size_t)(s3 * 8 + jg) * 512 + lane * 16);
                mma_f16(C3[j4],  (const uint32_t*)&A, B.x, B.y);
                mma_f16(C3m[j4], (const uint32_t*)&A, B.z, B.w);
            }
        }
        __syncthreads();   // S4: GEMM3 reads done before next tile's AB writes

        // ============ epilogue3: edges_out ==================================
        {
            int row = e0 + (wm << 4) + g;
            #pragma unroll
            for (int j4 = 0; j4 < 4; j4++) {
                int col = (((wn << 2) + j4) << 3) + (t << 1);
                float2 va, vb;
                va.x = fmaxf(C3[j4][0] + C3m[j4][0] * INV1024 + be[col],     0.f);
                va.y = fmaxf(C3[j4][1] + C3m[j4][1] * INV1024 + be[col + 1], 0.f);
                vb.x = fmaxf(C3[j4][2] + C3m[j4][2] * INV1024 + be[col],     0.f);
                vb.y = fmaxf(C3[j4][3] + C3m[j4][3] * INV1024 + be[col + 1], 0.f);
                *(float2*)(out_edges + (size_t)row       * DE + col) = va;
                *(float2*)(out_edges + (size_t)(row + 8) * DE + col) = vb;
            }
        }
    }
}

// ---------------------------------------------------------------------------
__global__ void finalize_kernel(float* __restrict__ out_nodes) {
    int i = blockIdx.x * blockDim.x + threadIdx.x;
    if (i < BN * (DN / 4)) {
        float c = g_cnts[i >> 4];
        float inv = (c > 0.f) ? (1.0f / c) : 0.f;
        float4 s = ((const float4*)g_sums)[i];
        s.x *= inv; s.y *= inv; s.z *= inv; s.w *= inv;
        ((float4*)out_nodes)[i] = s;
    }
}

__global__ void sr_kernel(const int* __restrict__ s, const int* __restrict__ r,
                          float* __restrict__ os, float* __restrict__ orr) {
    int i = blockIdx.x * blockDim.x + threadIdx.x;
    if (i < BE / 4) {
        int4 sv = ((const int4*)s)[i];
        int4 rv = ((const int4*)r)[i];
        float4 so, ro;
        so.x = (float)sv.x; so.y = (float)sv.y; so.z = (float)sv.z; so.w = (float)sv.w;
        ro.x = (float)rv.x; ro.y = (float)rv.y; ro.z = (float)rv.z; ro.w = (float)rv.w;
        ((float4*)os)[i]  = so;
        ((float4*)orr)[i] = ro;
    }
}

// ---------------------------------------------------------------------------
extern "C" void kernel_launch(void* const* d_in, const int* in_sizes, int n_in,
                              void* d_out, int out_size) {
    const float* nodes     = (const float*)d_in[0];
    const float* edges     = (const float*)d_in[1];
    const int*   senders   = (const int*)  d_in[2];
    const int*   receivers = (const int*)  d_in[3];
    const float* W_in      = (const float*)d_in[4];
    const float* b_in      = (const float*)d_in[5];
    const float* W_out     = (const float*)d_in[6];
    const float* b_out     = (const float*)d_in[7];
    const float* W_edge    = (const float*)d_in[8];
    const float* b_edge    = (const float*)d_in[9];

    float* out       = (float*)d_out;
    float* out_nodes = out;
    float* out_edges = out_nodes + (size_t)BN * DN;
    float* out_s     = out_edges + (size_t)BE * DE;
    float* out_r     = out_s + BE;

    cudaFuncSetAttribute(pnode_kernel,
                         cudaFuncAttributeMaxDynamicSharedMemorySize, PSM_TOTAL);
    cudaFuncSetAttribute(edge_kernel,
                         cudaFuncAttributeMaxDynamicSharedMemorySize, SMEM_TOTAL);

    int sm_count = 148;
    cudaDeviceGetAttribute(&sm_count, cudaDevAttrMultiProcessorCount, 0);

    zero_kernel<<<2048, 256>>>();
    pnode_kernel<<<BN / 128, PTHREADS, PSM_TOTAL>>>(nodes, W_in, b_in);
    edge_kernel<<<sm_count, THREADS, SMEM_TOTAL>>>(
        edges, senders, receivers,
        W_in, W_out, b_out, W_edge, b_edge, out_edges);
    finalize_kernel<<<(BN * DN / 4 + 255) / 256, 256>>>(out_nodes);
    sr_kernel<<<(BE / 4 + 255) / 256, 256>>>(senders, receivers, out_s, out_r);
}

// round 7
// speedup vs baseline: 5.5258x; 1.0920x over previous
#include <cuda_runtime.h>
#include <cuda_bf16.h>
#include <cuda_fp16.h>
#include <cstdint>

// Problem constants
#define NNODES 8192
#define DN  64
#define DE  64
#define IUU 128
#define BE  524288
#define BN  65536
#define TILE 128
#define NTILES (BE / TILE)     // 4096
#define THREADS 512

// Device-global scratch (no allocation allowed)
__device__ float g_sums[(size_t)BN * DN];    // 16 MB
__device__ float g_cnts[BN];
__device__ float g_P[(size_t)BN * 256];      // 64 MB: [P_r(128) || P_s(128)] per node

// ---------------- edge-kernel smem layout (bytes) ----------------
#define SM_RS   0                        // 2 x 128 ints (double buffered)
#define SM_SS   1024                     // 2 x 128 ints
#define SM_BO   2048                     // 64 f
#define SM_BE2  2304                     // 64 f
#define SM_W1   4096                     // W_in edge part, hi only: 64 frags * 256 = 16384
#define SM_W2   20480                    // W_out hi only: 64 frags * 256 = 16384
#define SM_W3   36864                    // W_edge hi only: 32 frags * 256 = 8192
#define SM_AB   45056                    // h frags 32768 (fp16); e frags overlay first 16384
#define SM_PING 77824                    // 2 x 16384 edge-chunk fp16 frag buffers
#define SMEM_TOTAL 110592

// ---------------- pnode-kernel smem layout (bf16 3-term, near-exact) ------
#define PSM_W   0                        // 4s*32j*512 = 65536
#define PSM_A   65536                    // 32768 (hi + mid@+16384)
#define PSM_B   98304                    // 128 f bias
#define PSM_TOTAL 98816
#define PTHREADS 256

// ---------------------------------------------------------------------------
__device__ __forceinline__ void mma_f16(float* c, const uint32_t* a,
                                        uint32_t b0, uint32_t b1) {
    asm volatile(
        "mma.sync.aligned.m16n8k16.row.col.f32.f16.f16.f32 "
        "{%0,%1,%2,%3},{%4,%5,%6,%7},{%8,%9},{%0,%1,%2,%3};"
        : "+f"(c[0]), "+f"(c[1]), "+f"(c[2]), "+f"(c[3])
        : "r"(a[0]), "r"(a[1]), "r"(a[2]), "r"(a[3]), "r"(b0), "r"(b1));
}

__device__ __forceinline__ void mma_bf16(float* c, const uint32_t* a,
                                         uint32_t b0, uint32_t b1) {
    asm volatile(
        "mma.sync.aligned.m16n8k16.row.col.f32.bf16.bf16.f32 "
        "{%0,%1,%2,%3},{%4,%5,%6,%7},{%8,%9},{%0,%1,%2,%3};"
        : "+f"(c[0]), "+f"(c[1]), "+f"(c[2]), "+f"(c[3])
        : "r"(a[0]), "r"(a[1]), "r"(a[2]), "r"(a[3]), "r"(b0), "r"(b1));
}

// fp32 pair -> packed fp16 pair
__device__ __forceinline__ uint32_t pack_h2(float x, float y) {
    __half2 h = __floats2half2_rn(x, y);
    return *reinterpret_cast<uint32_t*>(&h);
}
// bf16 split (for pnode)
__device__ __forceinline__ void split2(float x, float y, uint32_t& hi, uint32_t& mid) {
    __nv_bfloat162 h = __floats2bfloat162_rn(x, y);
    float rx = x - __bfloat162float(h.x);
    float ry = y - __bfloat162float(h.y);
    __nv_bfloat162 m = __floats2bfloat162_rn(rx, ry);
    hi  = *reinterpret_cast<uint32_t*>(&h);
    mid = *reinterpret_cast<uint32_t*>(&m);
}

// Weights -> fp16 B-frags, hi only (uint2/lane, 256B/frag). W [K, NT*8] row-major.
__device__ __forceinline__ void load_wfrag_h(const float* __restrict__ W, int K, int NT,
                                             char* dst, int wid, int lane, int nwarps) {
    const int g = lane >> 2, t = lane & 3;
    const int Nw = NT * 8;
    const int SF = K / 16;
    for (int f = wid; f < SF * NT; f += nwarps) {
        int s = f / NT, j = f - s * NT;
        int n = j * 8 + g;
        uint2 v;
        #pragma unroll
        for (int r = 0; r < 2; r++) {
            int k = s * 16 + 2 * t + 8 * r;
            ((uint32_t*)&v)[r] = pack_h2(W[(size_t)k * Nw + n], W[(size_t)(k + 1) * Nw + n]);
        }
        *(uint2*)(dst + (size_t)f * 256 + lane * 8) = v;
    }
}

// ---------------------------------------------------------------------------
__global__ void zero_kernel() {
    int stride = gridDim.x * blockDim.x;
    int i = blockIdx.x * blockDim.x + threadIdx.x;
    float4 z = make_float4(0.f, 0.f, 0.f, 0.f);
    for (int j = i; j < BN * DN / 4; j += stride) ((float4*)g_sums)[j] = z;
    for (int j = i; j < BN / 4; j += stride)      ((float4*)g_cnts)[j] = z;
}

// ---------------------------------------------------------------------------
// P[n][0:128)   = nodes[n] @ W_in[0:64]   + b_in
// P[n][128:256) = nodes[n] @ W_in[128:192]
__global__ __launch_bounds__(PTHREADS, 1)
void pnode_kernel(const float* __restrict__ nodes,
                  const float* __restrict__ W_in,
                  const float* __restrict__ b_in)
{
    extern __shared__ char sm[];
    const int tid  = threadIdx.x;
    const int lane = tid & 31;
    const int wid  = tid >> 5;
    const int g = lane >> 2, t = lane & 3;
    const int wm = wid & 3;
    const int wn = wid >> 2;

    for (int f = wid; f < 4 * 32; f += (PTHREADS / 32)) {
        int s = f >> 5, j = f & 31;
        int n = j * 8 + g;
        uint4 v;
        uint32_t* vp = (uint32_t*)&v;
        #pragma unroll
        for (int r = 0; r < 2; r++) {
            int k = s * 16 + 2 * t + 8 * r;
            float x, y;
            if (n < 128) { x = W_in[(size_t)k * IUU + n];         y = W_in[(size_t)(k + 1) * IUU + n]; }
            else         { x = W_in[(size_t)(128 + k) * IUU + n - 128];
                           y = W_in[(size_t)(129 + k) * IUU + n - 128]; }
            split2(x, y, vp[r], vp[2 + r]);
        }
        *(uint4*)(sm + PSM_W + (size_t)f * 512 + lane * 16) = v;
    }
    if (tid < IUU) ((float*)(sm + PSM_B))[tid] = b_in[tid];

    const int m0 = blockIdx.x * 128;
    #pragma unroll
    for (int ii = 0; ii < 16; ii++) {
        int idx = tid + ii * PTHREADS;
        int e = idx >> 5, j = idx & 31;
        float2 v = ((const float2*)(nodes + (size_t)(m0 + e) * DN))[j];
        uint32_t hi, mid;
        split2(v.x, v.y, hi, mid);
        int mt = e >> 4, sl = j >> 3;
        int ln = ((e & 7) << 2) | (j & 3);
        int rg = ((e >> 3) & 1) | (((j >> 2) & 1) << 1);
        char* p = sm + PSM_A + (((mt << 2) + sl) << 9) + ln * 16 + rg * 4;
        *(uint32_t*)p           = hi;
        *(uint32_t*)(p + 16384) = mid;
    }
    __syncthreads();

    const float* bi = (const float*)(sm + PSM_B);
    #pragma unroll
    for (int np = 0; np < 2; np++) {
        float C[2][8][4];
        #pragma unroll
        for (int a = 0; a < 2; a++)
            #pragma unroll
            for (int b = 0; b < 8; b++)
                #pragma unroll
                for (int c = 0; c < 4; c++) C[a][b][c] = 0.f;
        #pragma unroll
        for (int sl = 0; sl < 4; sl++) {
            uint4 Ah[2], Am[2];
            #pragma unroll
            for (int m2 = 0; m2 < 2; m2++) {
                int mt = (wm << 1) + m2;
                const char* p = sm + PSM_A + (((mt << 2) + sl) << 9) + lane * 16;
                Ah[m2] = *(const uint4*)p;
                Am[m2] = *(const uint4*)(p + 16384);
            }
            #pragma unroll
            for (int j8 = 0; j8 < 8; j8++) {
                int jg = wn * 16 + np * 8 + j8;
                uint4 B = *(const uint4*)(sm + PSM_W + (size_t)(sl * 32 + jg) * 512 + lane * 16);
                #pragma unroll
                for (int m2 = 0; m2 < 2; m2++) {
                    mma_bf16(C[m2][j8], (const uint32_t*)&Ah[m2], B.x, B.y);
                    mma_bf16(C[m2][j8], (const uint32_t*)&Ah[m2], B.z, B.w);
                    mma_bf16(C[m2][j8], (const uint32_t*)&Am[m2], B.x, B.y);
                }
            }
        }
        #pragma unroll
        for (int m2 = 0; m2 < 2; m2++) {
            int row = m0 + wm * 32 + m2 * 16 + g;
            #pragma unroll
            for (int j8 = 0; j8 < 8; j8++) {
                int col = (wn * 16 + np * 8 + j8) * 8 + t * 2;
                float bx = (col < 128) ? bi[col]     : 0.f;
                float by = (col < 128) ? bi[col + 1] : 0.f;
                float2 va, vb;
                va.x = C[m2][j8][0] + bx; va.y = C[m2][j8][1] + by;
                vb.x = C[m2][j8][2] + bx; vb.y = C[m2][j8][3] + by;
                *(float2*)(g_P + (size_t)row * 256 + col)       = va;
                *(float2*)(g_P + (size_t)(row + 8) * 256 + col) = vb;
            }
        }
    }
}

// ---------------------------------------------------------------------------
__global__ __launch_bounds__(THREADS, 1)
void edge_kernel(const float* __restrict__ edges,
                 const int*   __restrict__ senders,
                 const int*   __restrict__ receivers,
                 const float* __restrict__ W_in,
                 const float* __restrict__ W_out, const float* __restrict__ b_out,
                 const float* __restrict__ W_edge,const float* __restrict__ b_edge,
                 float* __restrict__ out_edges)
{
    extern __shared__ char sm[];
    const int tid  = threadIdx.x;
    const int lane = tid & 31;
    const int wid  = tid >> 5;
    const int g = lane >> 2, t = lane & 3;
    const int wm = wid & 7;                 // M band: rows 16*wm
    const int wn = wid >> 3;                // N half

    // one-time weights: all hi-only fp16 frags
    load_wfrag_h(W_in + 64 * IUU, 64, 16, sm + SM_W1, wid, lane, THREADS / 32);
    load_wfrag_h(W_out, 128, 8, sm + SM_W2, wid, lane, THREADS / 32);
    load_wfrag_h(W_edge, 64, 8, sm + SM_W3, wid, lane, THREADS / 32);
    if (tid < DN) ((float*)(sm + SM_BO))[tid]  = b_out[tid];
    if (tid < DE) ((float*)(sm + SM_BE2))[tid] = b_edge[tid];

    const float* bo = (const float*)(sm + SM_BO);
    const float* be = (const float*)(sm + SM_BE2);

    // prologue: tile0 indices + edge chunk (fp16) into buffer 0
    {
        int tile0 = blockIdx.x;
        if (tid < TILE) {
            int ge = tile0 * TILE + tid, b = ge >> 16;
            int nr = receivers[ge] + (b << 13);
            ((int*)(sm + SM_RS))[tid] = nr;
            ((int*)(sm + SM_SS))[tid] = senders[ge] + (b << 13);
            atomicAdd(&g_cnts[nr], 1.0f);
        }
        const float2* ebase = (const float2*)(edges + (size_t)tile0 * TILE * DE);
        #pragma unroll
        for (int ii = 0; ii < 8; ii++) {
            int idx = tid + ii * THREADS;
            float2 v = ebase[idx];
            int e = idx >> 5, j = idx & 31;
            int mt = e >> 4, sl = j >> 3;
            int ln = ((e & 7) << 2) | (j & 3);
            int rg = ((e >> 3) & 1) | (((j >> 2) & 1) << 1);
            *(uint32_t*)(sm + SM_PING + (((mt << 2) + sl) << 9) + ln * 16 + rg * 4) =
                pack_h2(v.x, v.y);
        }
    }
    __syncthreads();

    int pb = 0;
    for (int tile = blockIdx.x; tile < NTILES; tile += gridDim.x, pb ^= 1) {
        const int e0 = tile * TILE;
        const int* rs  = (const int*)(sm + SM_RS) + pb * TILE;
        const int* ssn = (const int*)(sm + SM_SS) + pb * TILE;

        // ---- prefetch next tile ----
        const int nt = tile + (int)gridDim.x;
        const bool valid = nt < NTILES;
        float2 ev[8];
        int nr = 0, nss = 0;
        if (valid) {
            const float2* ebase = (const float2*)(edges + (size_t)nt * TILE * DE);
            #pragma unroll
            for (int ii = 0; ii < 8; ii++) ev[ii] = ebase[tid + ii * THREADS];
            if (tid < TILE) {
                int ge = nt * TILE + tid, b = ge >> 16;
                nr  = receivers[ge] + (b << 13);
                nss = senders[ge]   + (b << 13);
            }
        }

        // ============ GEMM1 (edge chunk, 1-term): [128,64] @ W1h ============
        float C1[8][4];
        #pragma unroll
        for (int b = 0; b < 8; b++)
            #pragma unroll
            for (int c = 0; c < 4; c++) C1[b][c] = 0.f;
        {
            const char* abase = sm + SM_PING + pb * 16384;
            #pragma unroll
            for (int sl = 0; sl < 4; sl++) {
                uint4 A = *(const uint4*)(abase + (((wm << 2) + sl) << 9) + lane * 16);
                #pragma unroll
                for (int j8 = 0; j8 < 8; j8++) {
                    int jg = (wn << 3) + j8;
                    uint2 B = *(const uint2*)(sm + SM_W1 + (size_t)(sl * 16 + jg) * 256 + lane * 8);
                    mma_f16(C1[j8], (const uint32_t*)&A, B.x, B.y);
                }
            }
        }

        // ---- store prefetched chunk + indices ----
        if (valid) {
            #pragma unroll
            for (int ii = 0; ii < 8; ii++) {
                int idx = tid + ii * THREADS;
                int e = idx >> 5, j = idx & 31;
                int mt = e >> 4, sl = j >> 3;
                int ln = ((e & 7) << 2) | (j & 3);
                int rg = ((e >> 3) & 1) | (((j >> 2) & 1) << 1);
                *(uint32_t*)(sm + SM_PING + (pb ^ 1) * 16384 +
                             (((mt << 2) + sl) << 9) + ln * 16 + rg * 4) =
                    pack_h2(ev[ii].x, ev[ii].y);
            }
            if (tid < TILE) {
                ((int*)(sm + SM_RS))[(pb ^ 1) * TILE + tid] = nr;
                ((int*)(sm + SM_SS))[(pb ^ 1) * TILE + tid] = nss;
                atomicAdd(&g_cnts[nr], 1.0f);
            }
        }

        // ============ epilogue1: h = relu(C1 + P_r + P_s) -> fp16 frags =====
        {
            int r0 = (wm << 4) + g;
            const float2* Pra = (const float2*)(g_P + (size_t)rs[r0] * 256);
            const float2* Prb = (const float2*)(g_P + (size_t)rs[r0 + 8] * 256);
            const float2* Psa = (const float2*)(g_P + (size_t)ssn[r0] * 256) + 64;
            const float2* Psb = (const float2*)(g_P + (size_t)ssn[r0 + 8] * 256) + 64;
            #pragma unroll
            for (int jj = 0; jj < 2; jj++) {
                float2 va[4], vb[4], vc[4], vd[4];
                #pragma unroll
                for (int u = 0; u < 4; u++) {
                    int colf = ((wn << 3) + jj * 4 + u) * 4 + t;
                    va[u] = Pra[colf]; vb[u] = Prb[colf];
                    vc[u] = Psa[colf]; vd[u] = Psb[colf];
                }
                #pragma unroll
                for (int j8e = 0; j8e < 4; j8e += 2) {
                    uint4 H;
                    uint32_t* hp = (uint32_t*)&H;
                    #pragma unroll
                    for (int q = 0; q < 2; q++) {
                        int u = j8e + q;
                        int j8 = jj * 4 + u;
                        float v0 = fmaxf(C1[j8][0] + va[u].x + vc[u].x, 0.f);
                        float v1 = fmaxf(C1[j8][1] + va[u].y + vc[u].y, 0.f);
                        float v2 = fmaxf(C1[j8][2] + vb[u].x + vd[u].x, 0.f);
                        float v3 = fmaxf(C1[j8][3] + vb[u].y + vd[u].y, 0.f);
                        hp[q * 2 + 0] = pack_h2(v0, v1);
                        hp[q * 2 + 1] = pack_h2(v2, v3);
                    }
                    int sl2 = ((wn << 3) + jj * 4 + j8e) >> 1;
                    *(uint4*)(sm + SM_AB + (((wm << 3) + sl2) << 9) + lane * 16) = H;
                }
            }
        }
        __syncthreads();   // S1: h frags + prefetch stores visible

        // ============ GEMM2 (1-term): h[128,128] @ W_out ====================
        float C2[4][4];
        #pragma unroll
        for (int b = 0; b < 4; b++)
            #pragma unroll
            for (int c = 0; c < 4; c++) C2[b][c] = 0.f;
        #pragma unroll
        for (int s2 = 0; s2 < 8; s2++) {
            uint4 A = *(const uint4*)(sm + SM_AB + (((wm << 3) + s2) << 9) + lane * 16);
            #pragma unroll
            for (int j4 = 0; j4 < 4; j4++) {
                int jg = (wn << 2) + j4;
                uint2 B = *(const uint2*)(sm + SM_W2 + (size_t)(s2 * 8 + jg) * 256 + lane * 8);
                mma_f16(C2[j4], (const uint32_t*)&A, B.x, B.y);
            }
        }
        __syncthreads();   // S2: GEMM2 reads of AB done

        // ============ epilogue2: e_new -> atomics + fp16 e frags ============
        {
            int r0 = (wm << 4) + g;
            int n0 = rs[r0], n1 = rs[r0 + 8];
            #pragma unroll
            for (int j4e = 0; j4e < 4; j4e += 2) {
                uint4 E;
                uint32_t* ep = (uint32_t*)&E;
                #pragma unroll
                for (int q = 0; q < 2; q++) {
                    int j4 = j4e + q;
                    int col = (((wn << 2) + j4) << 3) + (t << 1);
                    float v0 = fmaxf(C2[j4][0] + bo[col],     0.f);
                    float v1 = fmaxf(C2[j4][1] + bo[col + 1], 0.f);
                    float v2 = fmaxf(C2[j4][2] + bo[col],     0.f);
                    float v3 = fmaxf(C2[j4][3] + bo[col + 1], 0.f);
                    atomicAdd(&g_sums[(size_t)n0 * DN + col],     v0);
                    atomicAdd(&g_sums[(size_t)n0 * DN + col + 1], v1);
                    atomicAdd(&g_sums[(size_t)n1 * DN + col],     v2);
                    atomicAdd(&g_sums[(size_t)n1 * DN + col + 1], v3);
                    ep[q * 2 + 0] = pack_h2(v0, v1);
                    ep[q * 2 + 1] = pack_h2(v2, v3);
                }
                int s3 = ((wn << 2) + j4e) >> 1;
                *(uint4*)(sm + SM_AB + (((wm << 2) + s3) << 9) + lane * 16) = E;
            }
        }
        __syncthreads();   // S3: e frags visible

        // ============ GEMM3 (1-term): e[128,64] @ W_edge ====================
        float C3[4][4];
        #pragma unroll
        for (int b = 0; b < 4; b++)
            #pragma unroll
            for (int c = 0; c < 4; c++) C3[b][c] = 0.f;
        #pragma unroll
        for (int s3 = 0; s3 < 4; s3++) {
            uint4 A = *(const uint4*)(sm + SM_AB + (((wm << 2) + s3) << 9) + lane * 16);
            #pragma unroll
            for (int j4 = 0; j4 < 4; j4++) {
                int jg = (wn << 2) + j4;
                uint2 B = *(const uint2*)(sm + SM_W3 + (size_t)(s3 * 8 + jg) * 256 + lane * 8);
                mma_f16(C3[j4], (const uint32_t*)&A, B.x, B.y);
            }
        }
        __syncthreads();   // S4: GEMM3 reads done before next tile's AB writes

        // ============ epilogue3: edges_out ==================================
        {
            int row = e0 + (wm << 4) + g;
            #pragma unroll
            for (int j4 = 0; j4 < 4; j4++) {
                int col = (((wn << 2) + j4) << 3) + (t << 1);
                float2 va, vb;
                va.x = fmaxf(C3[j4][0] + be[col],     0.f);
                va.y = fmaxf(C3[j4][1] + be[col + 1], 0.f);
                vb.x = fmaxf(C3[j4][2] + be[col],     0.f);
                vb.y = fmaxf(C3[j4][3] + be[col + 1], 0.f);
                *(float2*)(out_edges + (size_t)row       * DE + col) = va;
                *(float2*)(out_edges + (size_t)(row + 8) * DE + col) = vb;
            }
        }
    }
}

// ---------------------------------------------------------------------------
__global__ void finalize_kernel(float* __restrict__ out_nodes) {
    int i = blockIdx.x * blockDim.x + threadIdx.x;
    if (i < BN * (DN / 4)) {
        float c = g_cnts[i >> 4];
        float inv = (c > 0.f) ? (1.0f / c) : 0.f;
        float4 s = ((const float4*)g_sums)[i];
        s.x *= inv; s.y *= inv; s.z *= inv; s.w *= inv;
        ((float4*)out_nodes)[i] = s;
    }
}

__global__ void sr_kernel(const int* __restrict__ s, const int* __restrict__ r,
                          float* __restrict__ os, float* __restrict__ orr) {
    int i = blockIdx.x * blockDim.x + threadIdx.x;
    if (i < BE / 4) {
        int4 sv = ((const int4*)s)[i];
        int4 rv = ((const int4*)r)[i];
        float4 so, ro;
        so.x = (float)sv.x; so.y = (float)sv.y; so.z = (float)sv.z; so.w = (float)sv.w;
        ro.x = (float)rv.x; ro.y = (float)rv.y; ro.z = (float)rv.z; ro.w = (float)rv.w;
        ((float4*)os)[i]  = so;
        ((float4*)orr)[i] = ro;
    }
}

// ---------------------------------------------------------------------------
extern "C" void kernel_launch(void* const* d_in, const int* in_sizes, int n_in,
                              void* d_out, int out_size) {
    const float* nodes     = (const float*)d_in[0];
    const float* edges     = (const float*)d_in[1];
    const int*   senders   = (const int*)  d_in[2];
    const int*   receivers = (const int*)  d_in[3];
    const float* W_in      = (const float*)d_in[4];
    const float* b_in      = (const float*)d_in[5];
    const float* W_out     = (const float*)d_in[6];
    const float* b_out     = (const float*)d_in[7];
    const float* W_edge    = (const float*)d_in[8];
    const float* b_edge    = (const float*)d_in[9];

    float* out       = (float*)d_out;
    float* out_nodes = out;
    float* out_edges = out_nodes + (size_t)BN * DN;
    float* out_s     = out_edges + (size_t)BE * DE;
    float* out_r     = out_s + BE;

    cudaFuncSetAttribute(pnode_kernel,
                         cudaFuncAttributeMaxDynamicSharedMemorySize, PSM_TOTAL);
    cudaFuncSetAttribute(edge_kernel,
                         cudaFuncAttributeMaxDynamicSharedMemorySize, SMEM_TOTAL);

    int sm_count = 148;
    cudaDeviceGetAttribute(&sm_count, cudaDevAttrMultiProcessorCount, 0);

    zero_kernel<<<2048, 256>>>();
    pnode_kernel<<<BN / 128, PTHREADS, PSM_TOTAL>>>(nodes, W_in, b_in);
    edge_kernel<<<sm_count, THREADS, SMEM_TOTAL>>>(
        edges, senders, receivers,
        W_in, W_out, b_out, W_edge, b_edge, out_edges);
    finalize_kernel<<<(BN * DN / 4 + 255) / 256, 256>>>(out_nodes);
    sr_kernel<<<(BE / 4 + 255) / 256, 256>>>(senders, receivers, out_s, out_r);
}

// round 8
// speedup vs baseline: 5.7370x; 1.0382x over previous
#include <cuda_runtime.h>
#include <cuda_bf16.h>
#include <cuda_fp16.h>
#include <cstdint>

// Problem constants
#define NNODES 8192
#define DN  64
#define DE  64
#define IUU 128
#define BE  524288
#define BN  65536
#define TILE 128
#define NTILES (BE / TILE)     // 4096
#define THREADS 512

// Device-global scratch (no allocation allowed)
__device__ float    g_sums[(size_t)BN * DN];   // 16 MB
__device__ float    g_cnts[BN];
// fp16 P table, thread-swizzled: per node 128 uint32 = [Pr 64 | Ps 64] packs.
// pack index within half: t*16 + wn*8 + jj*4 + u  (see sw() mapping below)
__device__ uint32_t g_Ph[(size_t)BN * 128];    // 32 MB

// ---------------- edge-kernel smem layout (bytes) ----------------
#define SM_RS   0                        // 2 x 128 ints (double buffered)
#define SM_SS   1024                     // 2 x 128 ints
#define SM_BO   2048                     // 64 f
#define SM_BE2  2304                     // 64 f
#define SM_W1   4096                     // W_in edge part: 64 frags * 256 = 16384
#define SM_W2   20480                    // W_out: 64 frags * 256 = 16384
#define SM_W3   36864                    // W_edge: 32 frags * 256 = 8192
#define SM_AB   45056                    // h frags 32768 (fp16); e frags overlay first 16384
#define SM_PING 77824                    // 2 x 16384 edge-chunk fp16 frag buffers
#define SMEM_TOTAL 110592

// ---------------- pnode-kernel smem layout (bf16 3-term, near-exact) ------
#define PSM_W   0                        // 4s*32j*512 = 65536
#define PSM_A   65536                    // 32768 (hi + mid@+16384)
#define PSM_B   98304                    // 128 f bias
#define PSM_TOTAL 98816
#define PTHREADS 256

// ---------------------------------------------------------------------------
__device__ __forceinline__ void mma_f16(float* c, const uint32_t* a,
                                        uint32_t b0, uint32_t b1) {
    asm volatile(
        "mma.sync.aligned.m16n8k16.row.col.f32.f16.f16.f32 "
        "{%0,%1,%2,%3},{%4,%5,%6,%7},{%8,%9},{%0,%1,%2,%3};"
        : "+f"(c[0]), "+f"(c[1]), "+f"(c[2]), "+f"(c[3])
        : "r"(a[0]), "r"(a[1]), "r"(a[2]), "r"(a[3]), "r"(b0), "r"(b1));
}

__device__ __forceinline__ void mma_bf16(float* c, const uint32_t* a,
                                         uint32_t b0, uint32_t b1) {
    asm volatile(
        "mma.sync.aligned.m16n8k16.row.col.f32.bf16.bf16.f32 "
        "{%0,%1,%2,%3},{%4,%5,%6,%7},{%8,%9},{%0,%1,%2,%3};"
        : "+f"(c[0]), "+f"(c[1]), "+f"(c[2]), "+f"(c[3])
        : "r"(a[0]), "r"(a[1]), "r"(a[2]), "r"(a[3]), "r"(b0), "r"(b1));
}

__device__ __forceinline__ uint32_t pack_h2(float x, float y) {
    __half2 h = __floats2half2_rn(x, y);
    return *reinterpret_cast<uint32_t*>(&h);
}
__device__ __forceinline__ float2 h2f2(uint32_t w) {
    return __half22float2(*reinterpret_cast<__half2*>(&w));
}
// bf16 split (for pnode)
__device__ __forceinline__ void split2(float x, float y, uint32_t& hi, uint32_t& mid) {
    __nv_bfloat162 h = __floats2bfloat162_rn(x, y);
    float rx = x - __bfloat162float(h.x);
    float ry = y - __bfloat162float(h.y);
    __nv_bfloat162 m = __floats2bfloat162_rn(rx, ry);
    hi  = *reinterpret_cast<uint32_t*>(&h);
    mid = *reinterpret_cast<uint32_t*>(&m);
}

// Weights -> fp16 B-frags, hi only (uint2/lane, 256B/frag). W [K, NT*8] row-major.
__device__ __forceinline__ void load_wfrag_h(const float* __restrict__ W, int K, int NT,
                                             char* dst, int wid, int lane, int nwarps) {
    const int g = lane >> 2, t = lane & 3;
    const int Nw = NT * 8;
    const int SF = K / 16;
    for (int f = wid; f < SF * NT; f += nwarps) {
        int s = f / NT, j = f - s * NT;
        int n = j * 8 + g;
        uint2 v;
        #pragma unroll
        for (int r = 0; r < 2; r++) {
            int k = s * 16 + 2 * t + 8 * r;
            ((uint32_t*)&v)[r] = pack_h2(W[(size_t)k * Nw + n], W[(size_t)(k + 1) * Nw + n]);
        }
        *(uint2*)(dst + (size_t)f * 256 + lane * 8) = v;
    }
}

// ---------------------------------------------------------------------------
__global__ void zero_kernel() {
    int stride = gridDim.x * blockDim.x;
    int i = blockIdx.x * blockDim.x + threadIdx.x;
    float4 z = make_float4(0.f, 0.f, 0.f, 0.f);
    for (int j = i; j < BN * DN / 4; j += stride) ((float4*)g_sums)[j] = z;
    for (int j = i; j < BN / 4; j += stride)      ((float4*)g_cnts)[j] = z;
}

// ---------------------------------------------------------------------------
// Ph[n] = fp16([nodes[n]@W_in[0:64]+b_in  ||  nodes[n]@W_in[128:192]]), swizzled.
__global__ __launch_bounds__(PTHREADS, 1)
void pnode_kernel(const float* __restrict__ nodes,
                  const float* __restrict__ W_in,
                  const float* __restrict__ b_in)
{
    extern __shared__ char sm[];
    const int tid  = threadIdx.x;
    const int lane = tid & 31;
    const int wid  = tid >> 5;
    const int g = lane >> 2, t = lane & 3;
    const int wm = wid & 3;
    const int wn = wid >> 2;

    for (int f = wid; f < 4 * 32; f += (PTHREADS / 32)) {
        int s = f >> 5, j = f & 31;
        int n = j * 8 + g;
        uint4 v;
        uint32_t* vp = (uint32_t*)&v;
        #pragma unroll
        for (int r = 0; r < 2; r++) {
            int k = s * 16 + 2 * t + 8 * r;
            float x, y;
            if (n < 128) { x = W_in[(size_t)k * IUU + n];         y = W_in[(size_t)(k + 1) * IUU + n]; }
            else         { x = W_in[(size_t)(128 + k) * IUU + n - 128];
                           y = W_in[(size_t)(129 + k) * IUU + n - 128]; }
            split2(x, y, vp[r], vp[2 + r]);
        }
        *(uint4*)(sm + PSM_W + (size_t)f * 512 + lane * 16) = v;
    }
    if (tid < IUU) ((float*)(sm + PSM_B))[tid] = b_in[tid];

    const int m0 = blockIdx.x * 128;
    #pragma unroll
    for (int ii = 0; ii < 16; ii++) {
        int idx = tid + ii * PTHREADS;
        int e = idx >> 5, j = idx & 31;
        float2 v = ((const float2*)(nodes + (size_t)(m0 + e) * DN))[j];
        uint32_t hi, mid;
        split2(v.x, v.y, hi, mid);
        int mt = e >> 4, sl = j >> 3;
        int ln = ((e & 7) << 2) | (j & 3);
        int rg = ((e >> 3) & 1) | (((j >> 2) & 1) << 1);
        char* p = sm + PSM_A + (((mt << 2) + sl) << 9) + ln * 16 + rg * 4;
        *(uint32_t*)p           = hi;
        *(uint32_t*)(p + 16384) = mid;
    }
    __syncthreads();

    const float* bi = (const float*)(sm + PSM_B);
    #pragma unroll
    for (int np = 0; np < 2; np++) {
        float C[2][8][4];
        #pragma unroll
        for (int a = 0; a < 2; a++)
            #pragma unroll
            for (int b = 0; b < 8; b++)
                #pragma unroll
                for (int c = 0; c < 4; c++) C[a][b][c] = 0.f;
        #pragma unroll
        for (int sl = 0; sl < 4; sl++) {
            uint4 Ah[2], Am[2];
            #pragma unroll
            for (int m2 = 0; m2 < 2; m2++) {
                int mt = (wm << 1) + m2;
                const char* p = sm + PSM_A + (((mt << 2) + sl) << 9) + lane * 16;
                Ah[m2] = *(const uint4*)p;
                Am[m2] = *(const uint4*)(p + 16384);
            }
            #pragma unroll
            for (int j8 = 0; j8 < 8; j8++) {
                int jg = wn * 16 + np * 8 + j8;
                uint4 B = *(const uint4*)(sm + PSM_W + (size_t)(sl * 32 + jg) * 512 + lane * 16);
                #pragma unroll
                for (int m2 = 0; m2 < 2; m2++) {
                    mma_bf16(C[m2][j8], (const uint32_t*)&Ah[m2], B.x, B.y);
                    mma_bf16(C[m2][j8], (const uint32_t*)&Ah[m2], B.z, B.w);
                    mma_bf16(C[m2][j8], (const uint32_t*)&Am[m2], B.x, B.y);
                }
            }
        }
        #pragma unroll
        for (int m2 = 0; m2 < 2; m2++) {
            int row = m0 + wm * 32 + m2 * 16 + g;
            #pragma unroll
            for (int j8 = 0; j8 < 8; j8++) {
                int col = (wn * 16 + np * 8 + j8) * 8 + t * 2;
                float bx = (col < 128) ? bi[col]     : 0.f;
                float by = (col < 128) ? bi[col + 1] : 0.f;
                int half = col >> 7;
                int c = col & 127;
                // swizzle: pack index = t*16 + wn_e*8 + jj_e*4 + u_e
                int sw = ((c >> 1) & 3) * 16 + ((c >> 6) & 1) * 8 +
                         ((c >> 5) & 1) * 4 + ((c >> 3) & 3);
                g_Ph[(size_t)row * 128 + half * 64 + sw] =
                    pack_h2(C[m2][j8][0] + bx, C[m2][j8][1] + by);
                g_Ph[(size_t)(row + 8) * 128 + half * 64 + sw] =
                    pack_h2(C[m2][j8][2] + bx, C[m2][j8][3] + by);
            }
        }
    }
}

// ---------------------------------------------------------------------------
__global__ __launch_bounds__(THREADS, 1)
void edge_kernel(const float* __restrict__ edges,
                 const int*   __restrict__ senders,
                 const int*   __restrict__ receivers,
                 const float* __restrict__ W_in,
                 const float* __restrict__ W_out, const float* __restrict__ b_out,
                 const float* __restrict__ W_edge,const float* __restrict__ b_edge,
                 float* __restrict__ out_edges)
{
    extern __shared__ char sm[];
    const int tid  = threadIdx.x;
    const int lane = tid & 31;
    const int wid  = tid >> 5;
    const int g = lane >> 2, t = lane & 3;
    const int wm = wid & 7;                 // M band: rows 16*wm
    const int wn = wid >> 3;                // N half

    load_wfrag_h(W_in + 64 * IUU, 64, 16, sm + SM_W1, wid, lane, THREADS / 32);
    load_wfrag_h(W_out, 128, 8, sm + SM_W2, wid, lane, THREADS / 32);
    load_wfrag_h(W_edge, 64, 8, sm + SM_W3, wid, lane, THREADS / 32);
    if (tid < DN) ((float*)(sm + SM_BO))[tid]  = b_out[tid];
    if (tid < DE) ((float*)(sm + SM_BE2))[tid] = b_edge[tid];

    const float* bo = (const float*)(sm + SM_BO);
    const float* be = (const float*)(sm + SM_BE2);

    // prologue: tile0 indices + edge chunk (fp16) into buffer 0
    {
        int tile0 = blockIdx.x;
        if (tid < TILE) {
            int ge = tile0 * TILE + tid, b = ge >> 16;
            int nr = receivers[ge] + (b << 13);
            ((int*)(sm + SM_RS))[tid] = nr;
            ((int*)(sm + SM_SS))[tid] = senders[ge] + (b << 13);
            atomicAdd(&g_cnts[nr], 1.0f);
        }
        const float4* ebase = (const float4*)(edges + (size_t)tile0 * TILE * DE);
        #pragma unroll
        for (int ii = 0; ii < 4; ii++) {
            int idx = tid + ii * THREADS;           // float4 units, 2048 total
            float4 v = ebase[idx];
            int e = idx >> 4, jf = idx & 15;        // j pair: 2jf, 2jf+1
            int sl = jf >> 2;
            int rg = ((e >> 3) & 1) | (((jf >> 1) & 1) << 1);
            char* pbase = sm + SM_PING + (((e >> 4 << 2) + sl) << 9) + rg * 4;
            int j0 = 2 * jf;
            *(uint32_t*)(pbase + (((e & 7) << 2) | (j0 & 3)) * 16)       = pack_h2(v.x, v.y);
            *(uint32_t*)(pbase + (((e & 7) << 2) | ((j0 + 1) & 3)) * 16) = pack_h2(v.z, v.w);
        }
    }
    __syncthreads();

    int pb = 0;
    for (int tile = blockIdx.x; tile < NTILES; tile += gridDim.x, pb ^= 1) {
        const int e0 = tile * TILE;
        const int* rs  = (const int*)(sm + SM_RS) + pb * TILE;
        const int* ssn = (const int*)(sm + SM_SS) + pb * TILE;

        // ---- prefetch next tile ----
        const int nt = tile + (int)gridDim.x;
        const bool valid = nt < NTILES;
        float4 ev[4];
        int nr = 0, nss = 0;
        if (valid) {
            const float4* ebase = (const float4*)(edges + (size_t)nt * TILE * DE);
            #pragma unroll
            for (int ii = 0; ii < 4; ii++) ev[ii] = ebase[tid + ii * THREADS];
            if (tid < TILE) {
                int ge = nt * TILE + tid, b = ge >> 16;
                nr  = receivers[ge] + (b << 13);
                nss = senders[ge]   + (b << 13);
            }
        }

        // ============ GEMM1 (edge chunk, 1-term): [128,64] @ W1h ============
        float C1[8][4];
        #pragma unroll
        for (int b = 0; b < 8; b++)
            #pragma unroll
            for (int c = 0; c < 4; c++) C1[b][c] = 0.f;
        {
            const char* abase = sm + SM_PING + pb * 16384;
            #pragma unroll
            for (int sl = 0; sl < 4; sl++) {
                uint4 A = *(const uint4*)(abase + (((wm << 2) + sl) << 9) + lane * 16);
                #pragma unroll
                for (int j8 = 0; j8 < 8; j8++) {
                    int jg = (wn << 3) + j8;
                    uint2 B = *(const uint2*)(sm + SM_W1 + (size_t)(sl * 16 + jg) * 256 + lane * 8);
                    mma_f16(C1[j8], (const uint32_t*)&A, B.x, B.y);
                }
            }
        }

        // ---- store prefetched chunk + indices ----
        if (valid) {
            #pragma unroll
            for (int ii = 0; ii < 4; ii++) {
                int idx = tid + ii * THREADS;
                float4 v = ev[ii];
                int e = idx >> 4, jf = idx & 15;
                int sl = jf >> 2;
                int rg = ((e >> 3) & 1) | (((jf >> 1) & 1) << 1);
                char* pbase = sm + SM_PING + (pb ^ 1) * 16384 +
                              (((e >> 4 << 2) + sl) << 9) + rg * 4;
                int j0 = 2 * jf;
                *(uint32_t*)(pbase + (((e & 7) << 2) | (j0 & 3)) * 16)       = pack_h2(v.x, v.y);
                *(uint32_t*)(pbase + (((e & 7) << 2) | ((j0 + 1) & 3)) * 16) = pack_h2(v.z, v.w);
            }
            if (tid < TILE) {
                ((int*)(sm + SM_RS))[(pb ^ 1) * TILE + tid] = nr;
                ((int*)(sm + SM_SS))[(pb ^ 1) * TILE + tid] = nss;
                atomicAdd(&g_cnts[nr], 1.0f);
            }
        }

        // ============ epilogue1: h = relu(C1 + P_r + P_s) -> fp16 frags =====
        {
            int r0 = (wm << 4) + g;
            const int ra = rs[r0], rb = rs[r0 + 8];
            const int sa = ssn[r0], sb = ssn[r0 + 8];
            const int toff = t * 16 + wn * 8;
            #pragma unroll
            for (int jj = 0; jj < 2; jj++) {
                uint4 Ra = *(const uint4*)&g_Ph[(size_t)ra * 128 + toff + jj * 4];
                uint4 Rb = *(const uint4*)&g_Ph[(size_t)rb * 128 + toff + jj * 4];
                uint4 Sa = *(const uint4*)&g_Ph[(size_t)sa * 128 + 64 + toff + jj * 4];
                uint4 Sb = *(const uint4*)&g_Ph[(size_t)sb * 128 + 64 + toff + jj * 4];
                const uint32_t* pra = (const uint32_t*)&Ra;
                const uint32_t* prb = (const uint32_t*)&Rb;
                const uint32_t* psa = (const uint32_t*)&Sa;
                const uint32_t* psb = (const uint32_t*)&Sb;
                #pragma unroll
                for (int u2 = 0; u2 < 4; u2 += 2) {
                    uint4 H;
                    uint32_t* hp = (uint32_t*)&H;
                    #pragma unroll
                    for (int q = 0; q < 2; q++) {
                        int u = u2 + q;
                        int j8 = jj * 4 + u;
                        float2 fra = h2f2(pra[u]), frb = h2f2(prb[u]);
                        float2 fsa = h2f2(psa[u]), fsb = h2f2(psb[u]);
                        float v0 = fmaxf(C1[j8][0] + fra.x + fsa.x, 0.f);
                        float v1 = fmaxf(C1[j8][1] + fra.y + fsa.y, 0.f);
                        float v2 = fmaxf(C1[j8][2] + frb.x + fsb.x, 0.f);
                        float v3 = fmaxf(C1[j8][3] + frb.y + fsb.y, 0.f);
                        hp[q * 2 + 0] = pack_h2(v0, v1);
                        hp[q * 2 + 1] = pack_h2(v2, v3);
                    }
                    int sl2 = ((wn << 3) + jj * 4 + u2) >> 1;
                    *(uint4*)(sm + SM_AB + (((wm << 3) + sl2) << 9) + lane * 16) = H;
                }
            }
        }
        __syncthreads();   // S1: h frags + prefetch stores visible

        // ============ GEMM2 (1-term): h[128,128] @ W_out ====================
        float C2[4][4];
        #pragma unroll
        for (int b = 0; b < 4; b++)
            #pragma unroll
            for (int c = 0; c < 4; c++) C2[b][c] = 0.f;
        #pragma unroll
        for (int s2 = 0; s2 < 8; s2++) {
            uint4 A = *(const uint4*)(sm + SM_AB + (((wm << 3) + s2) << 9) + lane * 16);
            #pragma unroll
            for (int j4 = 0; j4 < 4; j4++) {
                int jg = (wn << 2) + j4;
                uint2 B = *(const uint2*)(sm + SM_W2 + (size_t)(s2 * 8 + jg) * 256 + lane * 8);
                mma_f16(C2[j4], (const uint32_t*)&A, B.x, B.y);
            }
        }
        __syncthreads();   // S2: GEMM2 reads of AB done

        // ============ epilogue2: e_new -> v2 atomics + fp16 e frags =========
        {
            int r0 = (wm << 4) + g;
            int n0 = rs[r0], n1 = rs[r0 + 8];
            #pragma unroll
            for (int j4e = 0; j4e < 4; j4e += 2) {
                uint4 E;
                uint32_t* ep = (uint32_t*)&E;
                #pragma unroll
                for (int q = 0; q < 2; q++) {
                    int j4 = j4e + q;
                    int col = (((wn << 2) + j4) << 3) + (t << 1);
                    float v0 = fmaxf(C2[j4][0] + bo[col],     0.f);
                    float v1 = fmaxf(C2[j4][1] + bo[col + 1], 0.f);
                    float v2 = fmaxf(C2[j4][2] + bo[col],     0.f);
                    float v3 = fmaxf(C2[j4][3] + bo[col + 1], 0.f);
                    atomicAdd((float2*)&g_sums[(size_t)n0 * DN + col], make_float2(v0, v1));
                    atomicAdd((float2*)&g_sums[(size_t)n1 * DN + col], make_float2(v2, v3));
                    ep[q * 2 + 0] = pack_h2(v0, v1);
                    ep[q * 2 + 1] = pack_h2(v2, v3);
                }
                int s3 = ((wn << 2) + j4e) >> 1;
                *(uint4*)(sm + SM_AB + (((wm << 2) + s3) << 9) + lane * 16) = E;
            }
        }
        __syncthreads();   // S3: e frags visible

        // ============ GEMM3 (1-term): e[128,64] @ W_edge ====================
        float C3[4][4];
        #pragma unroll
        for (int b = 0; b < 4; b++)
            #pragma unroll
            for (int c = 0; c < 4; c++) C3[b][c] = 0.f;
        #pragma unroll
        for (int s3 = 0; s3 < 4; s3++) {
            uint4 A = *(const uint4*)(sm + SM_AB + (((wm << 2) + s3) << 9) + lane * 16);
            #pragma unroll
            for (int j4 = 0; j4 < 4; j4++) {
                int jg = (wn << 2) + j4;
                uint2 B = *(const uint2*)(sm + SM_W3 + (size_t)(s3 * 8 + jg) * 256 + lane * 8);
                mma_f16(C3[j4], (const uint32_t*)&A, B.x, B.y);
            }
        }
        __syncthreads();   // S4: GEMM3 reads done before next tile's AB writes

        // ============ epilogue3: edges_out ==================================
        {
            int row = e0 + (wm << 4) + g;
            #pragma unroll
            for (int j4 = 0; j4 < 4; j4++) {
                int col = (((wn << 2) + j4) << 3) + (t << 1);
                float2 va, vb;
                va.x = fmaxf(C3[j4][0] + be[col],     0.f);
                va.y = fmaxf(C3[j4][1] + be[col + 1], 0.f);
                vb.x = fmaxf(C3[j4][2] + be[col],     0.f);
                vb.y = fmaxf(C3[j4][3] + be[col + 1], 0.f);
                *(float2*)(out_edges + (size_t)row       * DE + col) = va;
                *(float2*)(out_edges + (size_t)(row + 8) * DE + col) = vb;
            }
        }
    }
}

// ---------------------------------------------------------------------------
__global__ void finalize_kernel(float* __restrict__ out_nodes) {
    int i = blockIdx.x * blockDim.x + threadIdx.x;
    if (i < BN * (DN / 4)) {
        float c = g_cnts[i >> 4];
        float inv = (c > 0.f) ? (1.0f / c) : 0.f;
        float4 s = ((const float4*)g_sums)[i];
        s.x *= inv; s.y *= inv; s.z *= inv; s.w *= inv;
        ((float4*)out_nodes)[i] = s;
    }
}

__global__ void sr_kernel(const int* __restrict__ s, const int* __restrict__ r,
                          float* __restrict__ os, float* __restrict__ orr) {
    int i = blockIdx.x * blockDim.x + threadIdx.x;
    if (i < BE / 4) {
        int4 sv = ((const int4*)s)[i];
        int4 rv = ((const int4*)r)[i];
        float4 so, ro;
        so.x = (float)sv.x; so.y = (float)sv.y; so.z = (float)sv.z; so.w = (float)sv.w;
        ro.x = (float)rv.x; ro.y = (float)rv.y; ro.z = (float)rv.z; ro.w = (float)rv.w;
        ((float4*)os)[i]  = so;
        ((float4*)orr)[i] = ro;
    }
}

// ---------------------------------------------------------------------------
extern "C" void kernel_launch(void* const* d_in, const int* in_sizes, int n_in,
                              void* d_out, int out_size) {
    const float* nodes     = (const float*)d_in[0];
    const float* edges     = (const float*)d_in[1];
    const int*   senders   = (const int*)  d_in[2];
    const int*   receivers = (const int*)  d_in[3];
    const float* W_in      = (const float*)d_in[4];
    const float* b_in      = (const float*)d_in[5];
    const float* W_out     = (const float*)d_in[6];
    const float* b_out     = (const float*)d_in[7];
    const float* W_edge    = (const float*)d_in[8];
    const float* b_edge    = (const float*)d_in[9];

    float* out       = (float*)d_out;
    float* out_nodes = out;
    float* out_edges = out_nodes + (size_t)BN * DN;
    float* out_s     = out_edges + (size_t)BE * DE;
    float* out_r     = out_s + BE;

    cudaFuncSetAttribute(pnode_kernel,
                         cudaFuncAttributeMaxDynamicSharedMemorySize, PSM_TOTAL);
    cudaFuncSetAttribute(edge_kernel,
                         cudaFuncAttributeMaxDynamicSharedMemorySize, SMEM_TOTAL);

    int sm_count = 148;
    cudaDeviceGetAttribute(&sm_count, cudaDevAttrMultiProcessorCount, 0);

    zero_kernel<<<2048, 256>>>();
    pnode_kernel<<<BN / 128, PTHREADS, PSM_TOTAL>>>(nodes, W_in, b_in);
    edge_kernel<<<sm_count, THREADS, SMEM_TOTAL>>>(
        edges, senders, receivers,
        W_in, W_out, b_out, W_edge, b_edge, out_edges);
    finalize_kernel<<<(BN * DN / 4 + 255) / 256, 256>>>(out_nodes);
    sr_kernel<<<(BE / 4 + 255) / 256, 256>>>(senders, receivers, out_s, out_r);
}